// round 10
// baseline (speedup 1.0000x reference)
#include <cuda_runtime.h>
#include <math.h>

#define N_NODES 10000
#define N_EDGES 200000

// ---- output offsets (pytree leaf order) ----
#define OFF_X     0
#define OFF_LOSS  40000
#define OFF_BETA  40001
#define OFF_RES   40002
#define OFF_X1    240002
#define OFF_X2    1520002
#define OFF_X3    2800002
#define OFF_X4    4080002
#define OFF_E1    5360002
#define OFF_E2    30960002
#define OFF_E3    56560002
#define OFF_E4    82160002

// ---- scratch ----
__device__ float g_xsum[N_NODES * 128];   // zero-init at load; invariant: zero after each launch
__device__ int   g_cnt[N_NODES];
__device__ float g_loss[1];
__device__ float g_side[N_EDGES * 32];    // [eam(4) | zeros] tf32, edge-major
__device__ float g_nside[N_NODES * 32];   // [xorg(4) | zeros] tf32, node-major
__device__ float g_Yr[N_NODES * 128];
__device__ float g_Yc[N_NODES * 128];
__device__ float g_PW[76 * 4096];         // permuted tf32 weights

__device__ __forceinline__ unsigned f2tf32(float f) {
    unsigned u;
    asm("cvt.rna.tf32.f32 %0, %1;" : "=r"(u) : "f"(f));
    return u;
}
__device__ __forceinline__ float tf32f(float f) { return __uint_as_float(f2tf32(f)); }

__device__ __forceinline__ void red_add_v4(float* p, float4 v) {
    asm volatile("red.global.add.v4.f32 [%0], {%1,%2,%3,%4};"
                 :: "l"(p), "f"(v.x), "f"(v.y), "f"(v.z), "f"(v.w) : "memory");
}

__device__ __forceinline__ void qmul4(float qw,float qx,float qy,float qz,
                                      float rw,float rx,float ry,float rz,
                                      float& ow,float& ox,float& oy,float& oz) {
    ow = qw*rw - qx*rx - qy*ry - qz*rz;
    ox = qw*rx + qx*rw + qy*rz - qz*ry;
    oy = qw*ry - qx*rz + qy*rw + qz*rx;
    oz = qw*rz + qx*ry - qy*rx + qz*rw;
}

// ---------------- small kernels ----------------
__global__ void zero_f(float* p, int n) {
    int i = blockIdx.x * blockDim.x + threadIdx.x;
    if (i < n) p[i] = 0.f;
}
__global__ void zero_i(int* p, int n) {
    int i = blockIdx.x * blockDim.x + threadIdx.x;
    if (i < n) p[i] = 0;
}

// side (eam, tf32) + nside (xorg, tf32) + row counts
__global__ void prep_kernel(const float* __restrict__ x_org,
                            const float* __restrict__ edge_attr,
                            const int* __restrict__ row,
                            const int* __restrict__ col,
                            float* __restrict__ side,
                            float* __restrict__ nside,
                            int* __restrict__ cnt) {
    int e = blockIdx.x * blockDim.x + threadIdx.x;
    if (e < N_NODES) {
        float* s = nside + (size_t)e * 32;
        s[0]=tf32f(x_org[e*4+0]); s[1]=tf32f(x_org[e*4+1]);
        s[2]=tf32f(x_org[e*4+2]); s[3]=tf32f(x_org[e*4+3]);
#pragma unroll
        for (int i = 4; i < 32; i++) s[i] = 0.f;
    }
    if (e >= N_EDGES) return;
    int r = row[e], c = col[e];
    float cw = x_org[c*4+0], cx = -x_org[c*4+1], cy = -x_org[c*4+2], cz = -x_org[c*4+3];
    float aw = edge_attr[e*4+0], ax = edge_attr[e*4+1], ay = edge_attr[e*4+2], az = edge_attr[e*4+3];
    float tw,tx,ty,tz;
    qmul4(cw,cx,cy,cz, aw,ax,ay,az, tw,tx,ty,tz);
    float rw = x_org[r*4+0], rx = x_org[r*4+1], ry = x_org[r*4+2], rz = x_org[r*4+3];
    float ow,ox,oy,oz;
    qmul4(tw,tx,ty,tz, rw,rx,ry,rz, ow,ox,oy,oz);
    float* s = side + (size_t)e * 32;
    s[0]=tf32f(ow); s[1]=tf32f(ox); s[2]=tf32f(oy); s[3]=tf32f(oz);
#pragma unroll
    for (int i = 4; i < 32; i++) s[i] = 0.f;
    atomicAdd(&cnt[r], 1);
}

// ---- single-launch weight permuter for all 12 sub-GEMMs (76 chunks) ----
struct PermAll {
    const float* W[4];
    int chOff[13];
    int wsel[12];
    int nseg[12];
    int d0[12], s0[12], l0[12];
    int d1[12], s1[12], l1[12];
};
__global__ void permAll_kernel(const __grid_constant__ PermAll pp, float* __restrict__ PW) {
    int o = blockIdx.x * blockDim.x + threadIdx.x;
    if (o >= 76 * 4096) return;
    int gch = o >> 12, r = o & 4095;
    int slot = 0;
#pragma unroll
    for (int s = 0; s < 12; s++) if (gch >= pp.chOff[s+1]) slot = s + 1;
    int ch = gch - pp.chOff[slot];
    int wn = r >> 10, r2 = r & 1023;
    int ks = r2 >> 8, r3 = r2 & 255;
    int q  = r3 >> 7, r4 = r3 & 127;
    int lane = r4 >> 2, elem = r4 & 3;
    int g = lane >> 2, tg = lane & 3;
    int kp = ch*32 + ks*8 + tg + (elem & 1)*4;
    int n  = wn*32 + (2*q + (elem >> 1))*8 + g;
    const float* W = pp.W[pp.wsel[slot]];
    float v = 0.f;
    if (kp >= pp.d0[slot] && kp < pp.d0[slot] + pp.l0[slot])
        v = tf32f(W[(size_t)(pp.s0[slot] + kp - pp.d0[slot]) * 128 + n]);
    else if (pp.nseg[slot] > 1 && kp >= pp.d1[slot] && kp < pp.d1[slot] + pp.l1[slot])
        v = tf32f(W[(size_t)(pp.s1[slot] + kp - pp.d1[slot]) * 128 + n]);
    PW[o] = v;
}

// ---------------- contiguous-A tf32 GEMM (512 threads, in-fragment cvt) ----------------
struct Stage { const float* tab; int widthF; int strideF; int nCh; int shiftF; };
struct GP {
    Stage st[2]; int nSt; int totCh;
    const float* PW;  const float* PW2;
    const float* bias;
    const float* Yr; const float* Yc;
    float* e_out; float* xsum;
    const int* row; const int* col;
    int nRows;
    float* Yout; float* Yout2;
};

#define BM 128
#define A_BUF_F 16896     // 128 * 132
#define B_BUF_F 4096
#define SMEM_FLOATS (2*A_BUF_F + 2*B_BUF_F)
#define SMEM_BYTES  (SMEM_FLOATS*4 + 32)

__device__ __forceinline__ void bulk_g2s(unsigned dst, const float* src, unsigned bytes,
                                         unsigned mbar) {
    asm volatile(
        "cp.async.bulk.shared::cluster.global.mbarrier::complete_tx::bytes [%0], [%1], %2, [%3];"
        :: "r"(dst), "l"(src), "r"(bytes), "r"(mbar) : "memory");
}
__device__ __forceinline__ void mbar_init(unsigned mbar, unsigned cnt) {
    asm volatile("mbarrier.init.shared.b64 [%0], %1;" :: "r"(mbar), "r"(cnt) : "memory");
}
__device__ __forceinline__ void mbar_expect(unsigned mbar, unsigned bytes) {
    asm volatile("mbarrier.arrive.expect_tx.shared.b64 _, [%0], %1;"
                 :: "r"(mbar), "r"(bytes) : "memory");
}
__device__ __forceinline__ void mbar_wait(unsigned mbar, unsigned parity) {
    asm volatile(
        "{\n\t.reg .pred P;\n\t"
        "WAIT_%=:\n\t"
        "mbarrier.try_wait.parity.acquire.cta.shared::cta.b64 P, [%0], %1, 0x989680;\n\t"
        "@P bra.uni DONE_%=;\n\t"
        "bra.uni WAIT_%=;\n\t"
        "DONE_%=:\n\t}"
        :: "r"(mbar), "r"(parity) : "memory");
}

__global__ void __launch_bounds__(512, 1)
gemm_k(const __grid_constant__ GP p) {
    extern __shared__ __align__(16) float smem[];
    float* Abuf[2] = { smem, smem + A_BUF_F };
    float* Bbuf[2] = { smem + 2*A_BUF_F, smem + 2*A_BUF_F + B_BUF_F };
    unsigned mbase = (unsigned)__cvta_generic_to_shared(smem + SMEM_FLOATS);
    unsigned mbA[2] = { mbase, mbase + 8 };
    unsigned mbB[2] = { mbase + 16, mbase + 24 };
    unsigned AbufU[2] = { (unsigned)__cvta_generic_to_shared(Abuf[0]),
                          (unsigned)__cvta_generic_to_shared(Abuf[1]) };
    unsigned BbufU[2] = { (unsigned)__cvta_generic_to_shared(Bbuf[0]),
                          (unsigned)__cvta_generic_to_shared(Bbuf[1]) };

    const float* PW = blockIdx.y ? p.PW2 : p.PW;
    float* Yout = blockIdx.y ? p.Yout2 : p.Yout;

    int tid = threadIdx.x;
    int lane = tid & 31, wrp = tid >> 5;
    int r_base = blockIdx.x * BM;

    if (tid == 0) {
        mbar_init(mbA[0], 1); mbar_init(mbA[1], 1);
        mbar_init(mbB[0], 1); mbar_init(mbB[1], 1);
    }
    __syncthreads();

    int wm = wrp & 3, wn = wrp >> 2;
    int m0 = wm * 32, nb = wn * 32;
    int g = lane >> 2, tg = lane & 3;

    float acc[2][4][4];
#pragma unroll
    for (int mt = 0; mt < 2; mt++)
#pragma unroll
        for (int j = 0; j < 4; j++)
#pragma unroll
            for (int c = 0; c < 4; c++) acc[mt][j][c] = 0.f;

    auto issueA = [&](int s) {
        if (tid < 128) {
            Stage st = p.st[s];
            int idx = min(r_base + tid, p.nRows - 1);
            const float* src = st.tab + (size_t)idx * st.widthF - st.shiftF;
            unsigned bytes = (unsigned)(st.widthF + (st.shiftF ? 4 : 0)) * 4u;
            bulk_g2s(AbufU[s] + (unsigned)(tid * st.strideF * 4), src, bytes, mbA[s]);
            if (tid == 0) mbar_expect(mbA[s], 128u * bytes);
        }
    };
    auto issueB = [&](int gc) {
        if (tid == 0) {
            bulk_g2s(BbufU[gc & 1], PW + (size_t)gc * 4096, 16384, mbB[gc & 1]);
            mbar_expect(mbB[gc & 1], 16384);
        }
    };
    auto compute = [&](const float* As, int strideF, int kShift, int kkBase, const float* Bs) {
#pragma unroll
        for (int ks = 0; ks < 4; ks++) {
            int kk = kkBase + ks * 8 + kShift;
            unsigned a[2][4];
#pragma unroll
            for (int mt = 0; mt < 2; mt++) {
                int r = m0 + mt * 16;
                a[mt][0] = f2tf32(As[(r + g    ) * strideF + kk + tg    ]);
                a[mt][1] = f2tf32(As[(r + g + 8) * strideF + kk + tg    ]);
                a[mt][2] = f2tf32(As[(r + g    ) * strideF + kk + tg + 4]);
                a[mt][3] = f2tf32(As[(r + g + 8) * strideF + kk + tg + 4]);
            }
#pragma unroll
            for (int q = 0; q < 2; q++) {
                float4 bv = *reinterpret_cast<const float4*>(
                    &Bs[(((wn*4 + ks)*2 + q)*32 + lane)*4]);
                unsigned b00 = __float_as_uint(bv.x), b01 = __float_as_uint(bv.y);
                unsigned b10 = __float_as_uint(bv.z), b11 = __float_as_uint(bv.w);
                int j0 = 2*q, j1 = 2*q + 1;
#pragma unroll
                for (int mt = 0; mt < 2; mt++) {
                    asm volatile(
                        "mma.sync.aligned.m16n8k8.row.col.f32.tf32.tf32.f32 "
                        "{%0,%1,%2,%3}, {%4,%5,%6,%7}, {%8,%9}, {%0,%1,%2,%3};"
                        : "+f"(acc[mt][j0][0]), "+f"(acc[mt][j0][1]),
                          "+f"(acc[mt][j0][2]), "+f"(acc[mt][j0][3])
                        : "r"(a[mt][0]), "r"(a[mt][1]), "r"(a[mt][2]), "r"(a[mt][3]),
                          "r"(b00), "r"(b01));
                    asm volatile(
                        "mma.sync.aligned.m16n8k8.row.col.f32.tf32.tf32.f32 "
                        "{%0,%1,%2,%3}, {%4,%5,%6,%7}, {%8,%9}, {%0,%1,%2,%3};"
                        : "+f"(acc[mt][j1][0]), "+f"(acc[mt][j1][1]),
                          "+f"(acc[mt][j1][2]), "+f"(acc[mt][j1][3])
                        : "r"(a[mt][0]), "r"(a[mt][1]), "r"(a[mt][2]), "r"(a[mt][3]),
                          "r"(b10), "r"(b11));
                }
            }
        }
    };

    issueA(0);
    if (p.nSt > 1) issueA(1);
    issueB(0);
    if (p.totCh > 1) issueB(1);

    int gc = 0;
    for (int s = 0; s < p.nSt; s++) {
        mbar_wait(mbA[s], 0);
        const float* As = Abuf[s];
        int strideF = p.st[s].strideF;
        int kShift = p.st[s].shiftF;
        int nc = p.st[s].nCh;
        for (int c = 0; c < nc; c++, gc++) {
            mbar_wait(mbB[gc & 1], (gc >> 1) & 1);
            compute(As, strideF, kShift, c * 32, Bbuf[gc & 1]);
            __syncthreads();
            if (gc + 2 < p.totCh) issueB(gc + 2);
        }
    }

    // ---- epilogue: lane-paired float4 path ----
    // Pair lanes (tg even, tg odd) cover the SAME two edges; after shfl_xor(1),
    // even lane owns a contiguous float4 of edge A's columns, odd lane of edge B's.
    bool isEven = ((tg & 1) == 0);
    int tbase = nb + (isEven ? tg : (tg - 1)) * 2;

    if (Yout) {
#pragma unroll
        for (int mt = 0; mt < 2; mt++) {
            int nA = r_base + m0 + mt * 16 + g;
            int nS = isEven ? nA : (nA + 8);
            bool vS = nS < p.nRows;
#pragma unroll
            for (int j = 0; j < 4; j++) {
                float a0 = acc[mt][j][0], a1 = acc[mt][j][1];
                float b0 = acc[mt][j][2], b1 = acc[mt][j][3];
                float na0 = __shfl_xor_sync(0xFFFFFFFFu, a0, 1);
                float na1 = __shfl_xor_sync(0xFFFFFFFFu, a1, 1);
                float nb0 = __shfl_xor_sync(0xFFFFFFFFu, b0, 1);
                float nb1 = __shfl_xor_sync(0xFFFFFFFFu, b1, 1);
                float4 a4 = isEven ? make_float4(a0, a1, na0, na1)
                                   : make_float4(nb0, nb1, b0, b1);
                if (vS)
                    *reinterpret_cast<float4*>(&Yout[(size_t)nS*128 + tbase + j*8]) = a4;
            }
        }
    } else {
#pragma unroll
        for (int mt = 0; mt < 2; mt++) {
            int eA = r_base + m0 + mt * 16 + g;
            int eS = isEven ? eA : (eA + 8);
            bool vS = eS < N_EDGES;
            int rS = vS ? p.row[eS] : 0;
            int cS = vS ? p.col[eS] : 0;
#pragma unroll
            for (int j = 0; j < 4; j++) {
                float a0 = acc[mt][j][0], a1 = acc[mt][j][1];
                float b0 = acc[mt][j][2], b1 = acc[mt][j][3];
                float na0 = __shfl_xor_sync(0xFFFFFFFFu, a0, 1);
                float na1 = __shfl_xor_sync(0xFFFFFFFFu, a1, 1);
                float nb0 = __shfl_xor_sync(0xFFFFFFFFu, b0, 1);
                float nb1 = __shfl_xor_sync(0xFFFFFFFFu, b1, 1);
                if (vS) {
                    float4 a4 = isEven ? make_float4(a0, a1, na0, na1)
                                       : make_float4(nb0, nb1, b0, b1);
                    int n4 = tbase + j*8;
                    float4 bias4 = *reinterpret_cast<const float4*>(&p.bias[n4]);
                    float4 yr = *reinterpret_cast<const float4*>(&p.Yr[(size_t)rS*128 + n4]);
                    float4 yc = *reinterpret_cast<const float4*>(&p.Yc[(size_t)cS*128 + n4]);
                    float4 m4 = make_float4(a4.x + bias4.x + yr.x + yc.x,
                                            a4.y + bias4.y + yr.y + yc.y,
                                            a4.z + bias4.z + yr.z + yc.z,
                                            a4.w + bias4.w + yr.w + yc.w);
                    // e_out rows are only 8B-aligned (d_out offsets) -> float2 stores
                    *reinterpret_cast<float2*>(&p.e_out[(size_t)eS*128 + n4]) =
                        make_float2(fmaxf(m4.x, 0.f), fmaxf(m4.y, 0.f));
                    *reinterpret_cast<float2*>(&p.e_out[(size_t)eS*128 + n4 + 2]) =
                        make_float2(fmaxf(m4.z, 0.f), fmaxf(m4.w, 0.f));
                    red_add_v4(&p.xsum[(size_t)rS*128 + n4], m4);
                }
            }
        }
    }
}

// x_next = relu(xsum / max(cnt,1)); resets xsum
__global__ void node_update(float* __restrict__ xsum,
                            const int* __restrict__ cnt,
                            float* __restrict__ xout, int n_elems) {
    int i = blockIdx.x * blockDim.x + threadIdx.x;
    if (i >= n_elems) return;
    int node = i >> 7;
    float c = (float)max(cnt[node], 1);
    float v = xsum[i];
    xsum[i] = 0.f;
    xout[i] = fmaxf(v / c, 0.f);
}

__global__ void lin1_kernel(const float* __restrict__ x4,
                            const float* __restrict__ w,
                            const float* __restrict__ bb,
                            const float* __restrict__ x_org,
                            float* __restrict__ xout) {
    int n = blockIdx.x * blockDim.x + threadIdx.x;
    if (n >= N_NODES) return;
    float q0 = bb[0], q1 = bb[1], q2 = bb[2], q3 = bb[3];
    for (int k = 0; k < 128; k++) {
        float v = x4[(size_t)n * 128 + k];
        q0 = fmaf(v, w[k*4+0], q0);
        q1 = fmaf(v, w[k*4+1], q1);
        q2 = fmaf(v, w[k*4+2], q2);
        q3 = fmaf(v, w[k*4+3], q3);
    }
    float rw = x_org[n*4+0], rx = x_org[n*4+1], ry = x_org[n*4+2], rz = x_org[n*4+3];
    float ow,ox,oy,oz;
    qmul4(q0,q1,q2,q3, rw,rx,ry,rz, ow,ox,oy,oz);
    float nn = sqrtf(ow*ow + ox*ox + oy*oy + oz*oz);
    nn = fmaxf(nn, 1e-12f);
    xout[n*4+0] = ow/nn; xout[n*4+1] = ox/nn; xout[n*4+2] = oy/nn; xout[n*4+3] = oz/nn;
}

__global__ void loss_kernel(const float* __restrict__ gt,
                            const float* __restrict__ x,
                            const int* __restrict__ row,
                            const int* __restrict__ col,
                            const float* __restrict__ beta_p,
                            float* __restrict__ loss_acc) {
    int e = blockIdx.x * blockDim.x + threadIdx.x;
    float local = 0.f;
    if (e < N_EDGES) {
        int r = row[e], c = col[e];
        float aw = gt[c*4+0], ax = gt[c*4+1], ay = gt[c*4+2], az = gt[c*4+3];
        float bw = gt[r*4+0], bx = -gt[r*4+1], by = -gt[r*4+2], bz = -gt[r*4+3];
        float gw,gx,gy,gz;
        qmul4(aw,ax,ay,az, bw,bx,by,bz, gw,gx,gy,gz);
        float cw2 = x[c*4+0], cx2 = x[c*4+1], cy2 = x[c*4+2], cz2 = x[c*4+3];
        float dw = x[r*4+0], dx = -x[r*4+1], dy = -x[r*4+2], dz = -x[r*4+3];
        float xw,xx,xy,xz;
        qmul4(cw2,cx2,cy2,cz2, dw,dx,dy,dz, xw,xx,xy,xz);
        float lw,lx,ly,lz;
        qmul4(gw,-gx,-gy,-gz, xw,xx,xy,xz, lw,lx,ly,lz);
        float nn = sqrtf(lw*lw + lx*lx + ly*ly + lz*lz);
        nn = fmaxf(nn, 1e-12f);
        lw /= nn; lx /= nn; ly /= nn; lz /= nn;
        float beta = beta_p[0];
        float d[4] = {fabsf(lw - 1.f), fabsf(lx), fabsf(ly), fabsf(lz)};
#pragma unroll
        for (int i = 0; i < 4; i++) {
            float v = d[i];
            local += (v < beta) ? (0.5f * v * v / beta) : (v - 0.5f * beta);
        }
    }
    __shared__ float sm[256];
    sm[threadIdx.x] = local;
    __syncthreads();
    for (int s = 128; s > 0; s >>= 1) {
        if (threadIdx.x < s) sm[threadIdx.x] += sm[threadIdx.x + s];
        __syncthreads();
    }
    if (threadIdx.x == 0) atomicAdd(loss_acc, sm[0]);
}

__global__ void finalize_kernel(const float* __restrict__ loss_acc,
                                const float* __restrict__ beta_p,
                                float* __restrict__ out) {
    out[OFF_LOSS] = loss_acc[0] / (float)(N_EDGES * 4);
    out[OFF_BETA] = beta_p[0];
}

__global__ void outres_kernel(const float* __restrict__ e4,
                              const float* __restrict__ w,
                              const float* __restrict__ b,
                              float* __restrict__ out) {
    int gw = (blockIdx.x * blockDim.x + threadIdx.x) >> 5;
    int lane = threadIdx.x & 31;
    if (gw >= N_EDGES) return;
    float s = 0.f;
#pragma unroll
    for (int k = lane; k < 128; k += 32)
        s = fmaf(e4[(size_t)gw * 128 + k], w[k], s);
#pragma unroll
    for (int o = 16; o > 0; o >>= 1) s += __shfl_down_sync(0xFFFFFFFFu, s, o);
    if (lane == 0) out[OFF_RES + gw] = s + b[0];
}

// ---------------- host ----------------
extern "C" void kernel_launch(void* const* d_in, const int* in_sizes, int n_in,
                              void* d_out, int out_size) {
    const float* x_org     = (const float*)d_in[0];
    const float* edge_attr = (const float*)d_in[1];
    const float* gt_q      = (const float*)d_in[2];
    const float* beta      = (const float*)d_in[3];
    const float* node_feat = (const float*)d_in[4];
    const float* edge_feat = (const float*)d_in[5];
    const float* W1 = (const float*)d_in[6];
    const float* b1 = (const float*)d_in[7];
    const float* W2 = (const float*)d_in[8];
    const float* b2 = (const float*)d_in[9];
    const float* W3 = (const float*)d_in[10];
    const float* b3 = (const float*)d_in[11];
    const float* W4 = (const float*)d_in[12];
    const float* b4 = (const float*)d_in[13];
    const float* lin1_w = (const float*)d_in[14];
    const float* lin1_b = (const float*)d_in[15];
    const float* lin2_w = (const float*)d_in[16];
    const float* lin2_b = (const float*)d_in[17];
    const int* ei = (const int*)d_in[18];
    const int* row = ei;
    const int* col = ei + N_EDGES;

    float* out = (float*)d_out;
    float* x1 = out + OFF_X1;
    float* x2 = out + OFF_X2;
    float* x3 = out + OFF_X3;
    float* x4 = out + OFF_X4;
    float* e1 = out + OFF_E1;
    float* e2 = out + OFF_E2;
    float* e3 = out + OFF_E3;
    float* e4 = out + OFF_E4;

    float *xsum, *lossacc, *side, *nside, *PW, *Yr, *Yc;
    int* cnt;
    cudaGetSymbolAddress((void**)&xsum, g_xsum);
    cudaGetSymbolAddress((void**)&lossacc, g_loss);
    cudaGetSymbolAddress((void**)&cnt, g_cnt);
    cudaGetSymbolAddress((void**)&side, g_side);
    cudaGetSymbolAddress((void**)&nside, g_nside);
    cudaGetSymbolAddress((void**)&PW, g_PW);
    cudaGetSymbolAddress((void**)&Yr, g_Yr);
    cudaGetSymbolAddress((void**)&Yc, g_Yc);

    cudaFuncSetAttribute(gemm_k, cudaFuncAttributeMaxDynamicSharedMemorySize, SMEM_BYTES);

    zero_i<<<(N_NODES + 255)/256, 256>>>(cnt, N_NODES);
    zero_f<<<1, 32>>>(lossacc, 1);
    prep_kernel<<<(N_EDGES + 255)/256, 256>>>(x_org, edge_attr, row, col, side, nside, cnt);

    // ---- one-shot weight permute (12 slots, 76 chunks) ----
    int pwo[13];
    {
        PermAll pp;
        pp.W[0]=W1; pp.W[1]=W2; pp.W[2]=W3; pp.W[3]=W4;
        int counts[12] = {5,5,5,4,4,5,8,8,8,8,8,8};
        pp.chOff[0] = 0;
        for (int i = 0; i < 12; i++) pp.chOff[i+1] = pp.chOff[i] + counts[i];
        for (int i = 0; i < 13; i++) pwo[i] = pp.chOff[i];
        auto setS = [&](int s, int w, int ns, int d0,int s0,int l0, int d1,int s1,int l1) {
            pp.wsel[s]=w; pp.nseg[s]=ns;
            pp.d0[s]=d0; pp.s0[s]=s0; pp.l0[s]=l0;
            pp.d1[s]=d1; pp.s1[s]=s1; pp.l1[s]=l1;
        };
        setS(0, 0, 2, 0,0,128,   128,128,4);   // g1r: nf_r + xorg_r
        setS(1, 0, 2, 0,132,128, 128,260,4);   // g1c: nf_c + xorg_c
        setS(2, 0, 2, 0,264,128, 128,392,4);   // g1e: ef + eam
        setS(3, 1, 1, 0,0,128,   0,0,0);       // g2r
        setS(4, 1, 1, 0,128,128, 0,0,0);       // g2c
        setS(5, 1, 2, 0,260,128, 128,256,4);   // g2e: e1 + eam
        setS(6, 2, 1, 0,0,256,   0,0,0);       // g3r
        setS(7, 2, 1, 0,256,256, 0,0,0);       // g3c
        setS(8, 2, 1, 0,512,256, 0,0,0);       // g3e
        setS(9, 3, 1, 0,0,256,   0,0,0);       // g4r
        setS(10,3, 1, 0,256,256, 0,0,0);       // g4c
        setS(11,3, 1, 0,512,256, 0,0,0);       // g4e
        permAll_kernel<<<(76*4096 + 255)/256, 256>>>(pp, PW);
    }

    const int EGRID = (N_EDGES + BM - 1) / BM;
    const int NGRID = (N_NODES + BM - 1) / BM;

    auto node_pair = [&](int slotR, int slotC, const float* t0, int sh0,
                         const float* t1, int sh1, bool t1side) {
        GP p{};
        p.st[0] = { t0, 128, 132, 4, sh0 };
        if (t1side)   { p.st[1] = { t1, 32, 36, 1, 0 };    p.nSt = 2; p.totCh = 5; }
        else if (t1)  { p.st[1] = { t1, 128, 132, 4, sh1 }; p.nSt = 2; p.totCh = 8; }
        else          { p.nSt = 1; p.totCh = 4; }
        p.PW  = PW + (size_t)pwo[slotR]*4096;
        p.PW2 = PW + (size_t)pwo[slotC]*4096;
        p.nRows = N_NODES; p.Yout = Yr; p.Yout2 = Yc;
        gemm_k<<<dim3(NGRID, 2), 512, SMEM_BYTES>>>(p);
    };
    auto edge_gemm = [&](int slot, const float* t0, int sh0, const float* t1, int sh1,
                         bool t1side, const float* bias, float* e_out) {
        GP p{};
        p.st[0] = { t0, 128, 132, 4, sh0 };
        if (t1side) { p.st[1] = { t1, 32, 36, 1, 0 };    p.nSt = 2; p.totCh = 5; }
        else        { p.st[1] = { t1, 128, 132, 4, sh1 }; p.nSt = 2; p.totCh = 8; }
        p.PW = PW + (size_t)pwo[slot]*4096; p.PW2 = p.PW;
        p.bias = bias; p.Yr = Yr; p.Yc = Yc;
        p.e_out = e_out; p.xsum = xsum;
        p.row = row; p.col = col;
        p.nRows = N_EDGES; p.Yout = nullptr; p.Yout2 = nullptr;
        gemm_k<<<EGRID, 512, SMEM_BYTES>>>(p);
    };
    auto upd = [&](float* xout) {
        node_update<<<(N_NODES*128 + 255)/256, 256>>>(xsum, cnt, xout, N_NODES*128);
    };

    // Layer 1
    node_pair(0, 1, node_feat, 0, nside, 0, true);
    edge_gemm(2, edge_feat, 0, side, 0, true, b1, e1);
    upd(x1);
    // Layer 2
    node_pair(3, 4, x1, 2, nullptr, 0, false);
    edge_gemm(5, e1, 2, side, 0, true, b2, e2);
    upd(x2);
    // Layer 3
    node_pair(6, 7, x2, 2, x1, 2, false);
    edge_gemm(8, e2, 2, e1, 2, false, b3, e3);
    upd(x3);
    // Layer 4
    node_pair(9, 10, x3, 2, x2, 2, false);
    edge_gemm(11, e3, 2, e2, 2, false, b4, e4);
    upd(x4);

    lin1_kernel<<<(N_NODES + 255)/256, 256>>>(x4, lin1_w, lin1_b, x_org, out + OFF_X);
    loss_kernel<<<(N_EDGES + 255)/256, 256>>>(gt_q, out + OFF_X, row, col, beta, lossacc);
    finalize_kernel<<<1, 1>>>(lossacc, beta, out);
    outres_kernel<<<(N_EDGES*32 + 255)/256, 256>>>(e4, lin2_w, lin2_b, out);

    (void)in_sizes; (void)n_in; (void)out_size;
}

// round 11
// speedup vs baseline: 1.2608x; 1.2608x over previous
#include <cuda_runtime.h>
#include <math.h>

#define N_NODES 10000
#define N_EDGES 200000

// ---- output offsets (pytree leaf order) ----
#define OFF_X     0
#define OFF_LOSS  40000
#define OFF_BETA  40001
#define OFF_RES   40002
#define OFF_X1    240002
#define OFF_X2    1520002
#define OFF_X3    2800002
#define OFF_X4    4080002
#define OFF_E1    5360002
#define OFF_E2    30960002
#define OFF_E3    56560002
#define OFF_E4    82160002

// ---- scratch ----
__device__ float g_xsum[N_NODES * 128];   // zero-init at load; invariant: zero after each launch
__device__ int   g_cnt[N_NODES];
__device__ float g_loss[1];
__device__ float g_side[N_EDGES * 32];    // [eam(4) | zeros] tf32, edge-major
__device__ float g_nside[N_NODES * 32];   // [xorg(4) | zeros] tf32, node-major
__device__ float g_Yr[N_NODES * 128];
__device__ float g_Yc[N_NODES * 128];
__device__ float g_PW[76 * 4096];         // permuted tf32 weights

__device__ __forceinline__ unsigned f2tf32(float f) {
    unsigned u;
    asm("cvt.rna.tf32.f32 %0, %1;" : "=r"(u) : "f"(f));
    return u;
}
__device__ __forceinline__ float tf32f(float f) { return __uint_as_float(f2tf32(f)); }

__device__ __forceinline__ void red_add_v4(float* p, float4 v) {
    asm volatile("red.global.add.v4.f32 [%0], {%1,%2,%3,%4};"
                 :: "l"(p), "f"(v.x), "f"(v.y), "f"(v.z), "f"(v.w) : "memory");
}

__device__ __forceinline__ void qmul4(float qw,float qx,float qy,float qz,
                                      float rw,float rx,float ry,float rz,
                                      float& ow,float& ox,float& oy,float& oz) {
    ow = qw*rw - qx*rx - qy*ry - qz*rz;
    ox = qw*rx + qx*rw + qy*rz - qz*ry;
    oy = qw*ry - qx*rz + qy*rw + qz*rx;
    oz = qw*rz + qx*ry - qy*rx + qz*rw;
}

// ---------------- small kernels ----------------
__global__ void zero_f(float* p, int n) {
    int i = blockIdx.x * blockDim.x + threadIdx.x;
    if (i < n) p[i] = 0.f;
}
__global__ void zero_i(int* p, int n) {
    int i = blockIdx.x * blockDim.x + threadIdx.x;
    if (i < n) p[i] = 0;
}

// side (eam, tf32) + nside (xorg, tf32) + row counts
__global__ void prep_kernel(const float* __restrict__ x_org,
                            const float* __restrict__ edge_attr,
                            const int* __restrict__ row,
                            const int* __restrict__ col,
                            float* __restrict__ side,
                            float* __restrict__ nside,
                            int* __restrict__ cnt) {
    int e = blockIdx.x * blockDim.x + threadIdx.x;
    if (e < N_NODES) {
        float* s = nside + (size_t)e * 32;
        s[0]=tf32f(x_org[e*4+0]); s[1]=tf32f(x_org[e*4+1]);
        s[2]=tf32f(x_org[e*4+2]); s[3]=tf32f(x_org[e*4+3]);
#pragma unroll
        for (int i = 4; i < 32; i++) s[i] = 0.f;
    }
    if (e >= N_EDGES) return;
    int r = row[e], c = col[e];
    float cw = x_org[c*4+0], cx = -x_org[c*4+1], cy = -x_org[c*4+2], cz = -x_org[c*4+3];
    float aw = edge_attr[e*4+0], ax = edge_attr[e*4+1], ay = edge_attr[e*4+2], az = edge_attr[e*4+3];
    float tw,tx,ty,tz;
    qmul4(cw,cx,cy,cz, aw,ax,ay,az, tw,tx,ty,tz);
    float rw = x_org[r*4+0], rx = x_org[r*4+1], ry = x_org[r*4+2], rz = x_org[r*4+3];
    float ow,ox,oy,oz;
    qmul4(tw,tx,ty,tz, rw,rx,ry,rz, ow,ox,oy,oz);
    float* s = side + (size_t)e * 32;
    s[0]=tf32f(ow); s[1]=tf32f(ox); s[2]=tf32f(oy); s[3]=tf32f(oz);
#pragma unroll
    for (int i = 4; i < 32; i++) s[i] = 0.f;
    atomicAdd(&cnt[r], 1);
}

// ---- single-launch weight permuter for all 12 sub-GEMMs (76 chunks) ----
struct PermAll {
    const float* W[4];
    int chOff[13];
    int wsel[12];
    int nseg[12];
    int d0[12], s0[12], l0[12];
    int d1[12], s1[12], l1[12];
};
__global__ void permAll_kernel(const __grid_constant__ PermAll pp, float* __restrict__ PW) {
    int o = blockIdx.x * blockDim.x + threadIdx.x;
    if (o >= 76 * 4096) return;
    int gch = o >> 12, r = o & 4095;
    int slot = 0;
#pragma unroll
    for (int s = 0; s < 12; s++) if (gch >= pp.chOff[s+1]) slot = s + 1;
    int ch = gch - pp.chOff[slot];
    int wn = r >> 10, r2 = r & 1023;
    int ks = r2 >> 8, r3 = r2 & 255;
    int q  = r3 >> 7, r4 = r3 & 127;
    int lane = r4 >> 2, elem = r4 & 3;
    int g = lane >> 2, tg = lane & 3;
    int kp = ch*32 + ks*8 + tg + (elem & 1)*4;
    int n  = wn*32 + (2*q + (elem >> 1))*8 + g;
    const float* W = pp.W[pp.wsel[slot]];
    float v = 0.f;
    if (kp >= pp.d0[slot] && kp < pp.d0[slot] + pp.l0[slot])
        v = tf32f(W[(size_t)(pp.s0[slot] + kp - pp.d0[slot]) * 128 + n]);
    else if (pp.nseg[slot] > 1 && kp >= pp.d1[slot] && kp < pp.d1[slot] + pp.l1[slot])
        v = tf32f(W[(size_t)(pp.s1[slot] + kp - pp.d1[slot]) * 128 + n]);
    PW[o] = v;
}

// ---------------- contiguous-A tf32 GEMM (256 threads, 2 CTAs/SM) ----------------
struct Stage { const float* tab; int widthF; int strideF; int nCh; int shiftF; };
struct GP {
    Stage st[2]; int nSt; int totCh;
    const float* PW;  const float* PW2;
    const float* bias;
    const float* Yr; const float* Yc;
    float* e_out; float* xsum;
    const int* row; const int* col;
    int nRows;
    float* Yout; float* Yout2;
};

#define BM 128
#define A_BUF_F 16896     // 128 * 132 (single buffer, reused across stages)
#define B_BUF_F 4096
#define SMEM_FLOATS (A_BUF_F + 2*B_BUF_F)
#define SMEM_BYTES  (SMEM_FLOATS*4 + 32)

__device__ __forceinline__ void bulk_g2s(unsigned dst, const float* src, unsigned bytes,
                                         unsigned mbar) {
    asm volatile(
        "cp.async.bulk.shared::cluster.global.mbarrier::complete_tx::bytes [%0], [%1], %2, [%3];"
        :: "r"(dst), "l"(src), "r"(bytes), "r"(mbar) : "memory");
}
__device__ __forceinline__ void mbar_init(unsigned mbar, unsigned cnt) {
    asm volatile("mbarrier.init.shared.b64 [%0], %1;" :: "r"(mbar), "r"(cnt) : "memory");
}
__device__ __forceinline__ void mbar_expect(unsigned mbar, unsigned bytes) {
    asm volatile("mbarrier.arrive.expect_tx.shared.b64 _, [%0], %1;"
                 :: "r"(mbar), "r"(bytes) : "memory");
}
__device__ __forceinline__ void mbar_wait(unsigned mbar, unsigned parity) {
    asm volatile(
        "{\n\t.reg .pred P;\n\t"
        "WAIT_%=:\n\t"
        "mbarrier.try_wait.parity.acquire.cta.shared::cta.b64 P, [%0], %1, 0x989680;\n\t"
        "@P bra.uni DONE_%=;\n\t"
        "bra.uni WAIT_%=;\n\t"
        "DONE_%=:\n\t}"
        :: "r"(mbar), "r"(parity) : "memory");
}

__global__ void __launch_bounds__(256, 2)
gemm_k(const __grid_constant__ GP p) {
    extern __shared__ __align__(16) float smem[];
    float* Abuf = smem;
    float* Bbuf[2] = { smem + A_BUF_F, smem + A_BUF_F + B_BUF_F };
    unsigned mbase = (unsigned)__cvta_generic_to_shared(smem + SMEM_FLOATS);
    unsigned mbA = mbase;
    unsigned mbB[2] = { mbase + 8, mbase + 16 };
    unsigned AbufU = (unsigned)__cvta_generic_to_shared(Abuf);
    unsigned BbufU[2] = { (unsigned)__cvta_generic_to_shared(Bbuf[0]),
                          (unsigned)__cvta_generic_to_shared(Bbuf[1]) };

    const float* PW = blockIdx.y ? p.PW2 : p.PW;
    float* Yout = blockIdx.y ? p.Yout2 : p.Yout;

    int tid = threadIdx.x;
    int lane = tid & 31, wrp = tid >> 5;
    int r_base = blockIdx.x * BM;

    if (tid == 0) {
        mbar_init(mbA, 1);
        mbar_init(mbB[0], 1); mbar_init(mbB[1], 1);
    }
    __syncthreads();

    // 8 warps: warp (wm, wn) does 32 rows x 64 cols at (wm*32, wn*64)
    int wm = wrp & 3, wn = wrp >> 2;      // wn in {0,1}
    int m0 = wm * 32, nb = wn * 64;
    int g = lane >> 2, tg = lane & 3;

    float acc[2][8][4];
#pragma unroll
    for (int mt = 0; mt < 2; mt++)
#pragma unroll
        for (int j = 0; j < 8; j++)
#pragma unroll
            for (int c = 0; c < 4; c++) acc[mt][j][c] = 0.f;

    auto issueA = [&](int s) {
        if (tid < 128) {
            Stage st = p.st[s];
            int idx = min(r_base + tid, p.nRows - 1);
            const float* src = st.tab + (size_t)idx * st.widthF - st.shiftF;
            unsigned bytes = (unsigned)(st.widthF + (st.shiftF ? 4 : 0)) * 4u;
            bulk_g2s(AbufU + (unsigned)(tid * st.strideF * 4), src, bytes, mbA);
            if (tid == 0) mbar_expect(mbA, 128u * bytes);
        }
    };
    auto issueB = [&](int gc) {
        if (tid == 0) {
            bulk_g2s(BbufU[gc & 1], PW + (size_t)gc * 4096, 16384, mbB[gc & 1]);
            mbar_expect(mbB[gc & 1], 16384);
        }
    };
    auto compute = [&](int strideF, int kShift, int kkBase, const float* Bs) {
#pragma unroll
        for (int ks = 0; ks < 4; ks++) {
            int kk = kkBase + ks * 8 + kShift;
            unsigned a[2][4];
#pragma unroll
            for (int mt = 0; mt < 2; mt++) {
                int r = m0 + mt * 16;
                a[mt][0] = f2tf32(Abuf[(r + g    ) * strideF + kk + tg    ]);
                a[mt][1] = f2tf32(Abuf[(r + g + 8) * strideF + kk + tg    ]);
                a[mt][2] = f2tf32(Abuf[(r + g    ) * strideF + kk + tg + 4]);
                a[mt][3] = f2tf32(Abuf[(r + g + 8) * strideF + kk + tg + 4]);
            }
#pragma unroll
            for (int sub = 0; sub < 2; sub++) {
                int wnG = wn * 2 + sub;
#pragma unroll
                for (int q = 0; q < 2; q++) {
                    float4 bv = *reinterpret_cast<const float4*>(
                        &Bs[(((wnG*4 + ks)*2 + q)*32 + lane)*4]);
                    unsigned b00 = __float_as_uint(bv.x), b01 = __float_as_uint(bv.y);
                    unsigned b10 = __float_as_uint(bv.z), b11 = __float_as_uint(bv.w);
                    int j0 = sub*4 + 2*q, j1 = j0 + 1;
#pragma unroll
                    for (int mt = 0; mt < 2; mt++) {
                        asm volatile(
                            "mma.sync.aligned.m16n8k8.row.col.f32.tf32.tf32.f32 "
                            "{%0,%1,%2,%3}, {%4,%5,%6,%7}, {%8,%9}, {%0,%1,%2,%3};"
                            : "+f"(acc[mt][j0][0]), "+f"(acc[mt][j0][1]),
                              "+f"(acc[mt][j0][2]), "+f"(acc[mt][j0][3])
                            : "r"(a[mt][0]), "r"(a[mt][1]), "r"(a[mt][2]), "r"(a[mt][3]),
                              "r"(b00), "r"(b01));
                        asm volatile(
                            "mma.sync.aligned.m16n8k8.row.col.f32.tf32.tf32.f32 "
                            "{%0,%1,%2,%3}, {%4,%5,%6,%7}, {%8,%9}, {%0,%1,%2,%3};"
                            : "+f"(acc[mt][j1][0]), "+f"(acc[mt][j1][1]),
                              "+f"(acc[mt][j1][2]), "+f"(acc[mt][j1][3])
                            : "r"(a[mt][0]), "r"(a[mt][1]), "r"(a[mt][2]), "r"(a[mt][3]),
                              "r"(b10), "r"(b11));
                    }
                }
            }
        }
    };

    issueA(0);
    issueB(0);
    if (p.totCh > 1) issueB(1);

    int gc = 0;
    for (int s = 0; s < p.nSt; s++) {
        mbar_wait(mbA, s & 1);            // stage s completes phase s
        int strideF = p.st[s].strideF;
        int kShift = p.st[s].shiftF;
        int nc = p.st[s].nCh;
        for (int c = 0; c < nc; c++, gc++) {
            mbar_wait(mbB[gc & 1], (gc >> 1) & 1);
            compute(strideF, kShift, c * 32, Bbuf[gc & 1]);
            __syncthreads();              // all warps done with this B buf (and A on last chunk)
            if (gc + 2 < p.totCh) issueB(gc + 2);
            if (c == nc - 1 && s + 1 < p.nSt) issueA(s + 1);  // reload A buffer for next stage
        }
    }

    // ---- epilogue: lane-paired float4 path ----
    bool isEven = ((tg & 1) == 0);
    int tbase = nb + (isEven ? tg : (tg - 1)) * 2;

    if (Yout) {
#pragma unroll
        for (int mt = 0; mt < 2; mt++) {
            int nA = r_base + m0 + mt * 16 + g;
            int nS = isEven ? nA : (nA + 8);
            bool vS = nS < p.nRows;
#pragma unroll
            for (int j = 0; j < 8; j++) {
                float a0 = acc[mt][j][0], a1 = acc[mt][j][1];
                float b0 = acc[mt][j][2], b1 = acc[mt][j][3];
                float na0 = __shfl_xor_sync(0xFFFFFFFFu, a0, 1);
                float na1 = __shfl_xor_sync(0xFFFFFFFFu, a1, 1);
                float nb0 = __shfl_xor_sync(0xFFFFFFFFu, b0, 1);
                float nb1 = __shfl_xor_sync(0xFFFFFFFFu, b1, 1);
                float4 a4 = isEven ? make_float4(a0, a1, na0, na1)
                                   : make_float4(nb0, nb1, b0, b1);
                if (vS)
                    *reinterpret_cast<float4*>(&Yout[(size_t)nS*128 + tbase + j*8]) = a4;
            }
        }
    } else {
#pragma unroll
        for (int mt = 0; mt < 2; mt++) {
            int eA = r_base + m0 + mt * 16 + g;
            int eS = isEven ? eA : (eA + 8);
            bool vS = eS < N_EDGES;
            int rS = vS ? p.row[eS] : 0;
            int cS = vS ? p.col[eS] : 0;
#pragma unroll
            for (int j = 0; j < 8; j++) {
                float a0 = acc[mt][j][0], a1 = acc[mt][j][1];
                float b0 = acc[mt][j][2], b1 = acc[mt][j][3];
                float na0 = __shfl_xor_sync(0xFFFFFFFFu, a0, 1);
                float na1 = __shfl_xor_sync(0xFFFFFFFFu, a1, 1);
                float nb0 = __shfl_xor_sync(0xFFFFFFFFu, b0, 1);
                float nb1 = __shfl_xor_sync(0xFFFFFFFFu, b1, 1);
                if (vS) {
                    float4 a4 = isEven ? make_float4(a0, a1, na0, na1)
                                       : make_float4(nb0, nb1, b0, b1);
                    int n4 = tbase + j*8;
                    float4 bias4 = *reinterpret_cast<const float4*>(&p.bias[n4]);
                    float4 yr = *reinterpret_cast<const float4*>(&p.Yr[(size_t)rS*128 + n4]);
                    float4 yc = *reinterpret_cast<const float4*>(&p.Yc[(size_t)cS*128 + n4]);
                    float4 m4 = make_float4(a4.x + bias4.x + yr.x + yc.x,
                                            a4.y + bias4.y + yr.y + yc.y,
                                            a4.z + bias4.z + yr.z + yc.z,
                                            a4.w + bias4.w + yr.w + yc.w);
                    *reinterpret_cast<float2*>(&p.e_out[(size_t)eS*128 + n4]) =
                        make_float2(fmaxf(m4.x, 0.f), fmaxf(m4.y, 0.f));
                    *reinterpret_cast<float2*>(&p.e_out[(size_t)eS*128 + n4 + 2]) =
                        make_float2(fmaxf(m4.z, 0.f), fmaxf(m4.w, 0.f));
                    red_add_v4(&p.xsum[(size_t)rS*128 + n4], m4);
                }
            }
        }
    }
}

// x_next = relu(xsum / max(cnt,1)); resets xsum
__global__ void node_update(float* __restrict__ xsum,
                            const int* __restrict__ cnt,
                            float* __restrict__ xout, int n_elems) {
    int i = blockIdx.x * blockDim.x + threadIdx.x;
    if (i >= n_elems) return;
    int node = i >> 7;
    float c = (float)max(cnt[node], 1);
    float v = xsum[i];
    xsum[i] = 0.f;
    xout[i] = fmaxf(v / c, 0.f);
}

__global__ void lin1_kernel(const float* __restrict__ x4,
                            const float* __restrict__ w,
                            const float* __restrict__ bb,
                            const float* __restrict__ x_org,
                            float* __restrict__ xout) {
    int n = blockIdx.x * blockDim.x + threadIdx.x;
    if (n >= N_NODES) return;
    float q0 = bb[0], q1 = bb[1], q2 = bb[2], q3 = bb[3];
    for (int k = 0; k < 128; k++) {
        float v = x4[(size_t)n * 128 + k];
        q0 = fmaf(v, w[k*4+0], q0);
        q1 = fmaf(v, w[k*4+1], q1);
        q2 = fmaf(v, w[k*4+2], q2);
        q3 = fmaf(v, w[k*4+3], q3);
    }
    float rw = x_org[n*4+0], rx = x_org[n*4+1], ry = x_org[n*4+2], rz = x_org[n*4+3];
    float ow,ox,oy,oz;
    qmul4(q0,q1,q2,q3, rw,rx,ry,rz, ow,ox,oy,oz);
    float nn = sqrtf(ow*ow + ox*ox + oy*oy + oz*oz);
    nn = fmaxf(nn, 1e-12f);
    xout[n*4+0] = ow/nn; xout[n*4+1] = ox/nn; xout[n*4+2] = oy/nn; xout[n*4+3] = oz/nn;
}

__global__ void loss_kernel(const float* __restrict__ gt,
                            const float* __restrict__ x,
                            const int* __restrict__ row,
                            const int* __restrict__ col,
                            const float* __restrict__ beta_p,
                            float* __restrict__ loss_acc) {
    int e = blockIdx.x * blockDim.x + threadIdx.x;
    float local = 0.f;
    if (e < N_EDGES) {
        int r = row[e], c = col[e];
        float aw = gt[c*4+0], ax = gt[c*4+1], ay = gt[c*4+2], az = gt[c*4+3];
        float bw = gt[r*4+0], bx = -gt[r*4+1], by = -gt[r*4+2], bz = -gt[r*4+3];
        float gw,gx,gy,gz;
        qmul4(aw,ax,ay,az, bw,bx,by,bz, gw,gx,gy,gz);
        float cw2 = x[c*4+0], cx2 = x[c*4+1], cy2 = x[c*4+2], cz2 = x[c*4+3];
        float dw = x[r*4+0], dx = -x[r*4+1], dy = -x[r*4+2], dz = -x[r*4+3];
        float xw,xx,xy,xz;
        qmul4(cw2,cx2,cy2,cz2, dw,dx,dy,dz, xw,xx,xy,xz);
        float lw,lx,ly,lz;
        qmul4(gw,-gx,-gy,-gz, xw,xx,xy,xz, lw,lx,ly,lz);
        float nn = sqrtf(lw*lw + lx*lx + ly*ly + lz*lz);
        nn = fmaxf(nn, 1e-12f);
        lw /= nn; lx /= nn; ly /= nn; lz /= nn;
        float beta = beta_p[0];
        float d[4] = {fabsf(lw - 1.f), fabsf(lx), fabsf(ly), fabsf(lz)};
#pragma unroll
        for (int i = 0; i < 4; i++) {
            float v = d[i];
            local += (v < beta) ? (0.5f * v * v / beta) : (v - 0.5f * beta);
        }
    }
    __shared__ float sm[256];
    sm[threadIdx.x] = local;
    __syncthreads();
    for (int s = 128; s > 0; s >>= 1) {
        if (threadIdx.x < s) sm[threadIdx.x] += sm[threadIdx.x + s];
        __syncthreads();
    }
    if (threadIdx.x == 0) atomicAdd(loss_acc, sm[0]);
}

__global__ void finalize_kernel(const float* __restrict__ loss_acc,
                                const float* __restrict__ beta_p,
                                float* __restrict__ out) {
    out[OFF_LOSS] = loss_acc[0] / (float)(N_EDGES * 4);
    out[OFF_BETA] = beta_p[0];
}

__global__ void outres_kernel(const float* __restrict__ e4,
                              const float* __restrict__ w,
                              const float* __restrict__ b,
                              float* __restrict__ out) {
    int gw = (blockIdx.x * blockDim.x + threadIdx.x) >> 5;
    int lane = threadIdx.x & 31;
    if (gw >= N_EDGES) return;
    float s = 0.f;
#pragma unroll
    for (int k = lane; k < 128; k += 32)
        s = fmaf(e4[(size_t)gw * 128 + k], w[k], s);
#pragma unroll
    for (int o = 16; o > 0; o >>= 1) s += __shfl_down_sync(0xFFFFFFFFu, s, o);
    if (lane == 0) out[OFF_RES + gw] = s + b[0];
}

// ---------------- host ----------------
extern "C" void kernel_launch(void* const* d_in, const int* in_sizes, int n_in,
                              void* d_out, int out_size) {
    const float* x_org     = (const float*)d_in[0];
    const float* edge_attr = (const float*)d_in[1];
    const float* gt_q      = (const float*)d_in[2];
    const float* beta      = (const float*)d_in[3];
    const float* node_feat = (const float*)d_in[4];
    const float* edge_feat = (const float*)d_in[5];
    const float* W1 = (const float*)d_in[6];
    const float* b1 = (const float*)d_in[7];
    const float* W2 = (const float*)d_in[8];
    const float* b2 = (const float*)d_in[9];
    const float* W3 = (const float*)d_in[10];
    const float* b3 = (const float*)d_in[11];
    const float* W4 = (const float*)d_in[12];
    const float* b4 = (const float*)d_in[13];
    const float* lin1_w = (const float*)d_in[14];
    const float* lin1_b = (const float*)d_in[15];
    const float* lin2_w = (const float*)d_in[16];
    const float* lin2_b = (const float*)d_in[17];
    const int* ei = (const int*)d_in[18];
    const int* row = ei;
    const int* col = ei + N_EDGES;

    float* out = (float*)d_out;
    float* x1 = out + OFF_X1;
    float* x2 = out + OFF_X2;
    float* x3 = out + OFF_X3;
    float* x4 = out + OFF_X4;
    float* e1 = out + OFF_E1;
    float* e2 = out + OFF_E2;
    float* e3 = out + OFF_E3;
    float* e4 = out + OFF_E4;

    float *xsum, *lossacc, *side, *nside, *PW, *Yr, *Yc;
    int* cnt;
    cudaGetSymbolAddress((void**)&xsum, g_xsum);
    cudaGetSymbolAddress((void**)&lossacc, g_loss);
    cudaGetSymbolAddress((void**)&cnt, g_cnt);
    cudaGetSymbolAddress((void**)&side, g_side);
    cudaGetSymbolAddress((void**)&nside, g_nside);
    cudaGetSymbolAddress((void**)&PW, g_PW);
    cudaGetSymbolAddress((void**)&Yr, g_Yr);
    cudaGetSymbolAddress((void**)&Yc, g_Yc);

    cudaFuncSetAttribute(gemm_k, cudaFuncAttributeMaxDynamicSharedMemorySize, SMEM_BYTES);

    zero_i<<<(N_NODES + 255)/256, 256>>>(cnt, N_NODES);
    zero_f<<<1, 32>>>(lossacc, 1);
    prep_kernel<<<(N_EDGES + 255)/256, 256>>>(x_org, edge_attr, row, col, side, nside, cnt);

    // ---- one-shot weight permute (12 slots, 76 chunks) ----
    int pwo[13];
    {
        PermAll pp;
        pp.W[0]=W1; pp.W[1]=W2; pp.W[2]=W3; pp.W[3]=W4;
        int counts[12] = {5,5,5,4,4,5,8,8,8,8,8,8};
        pp.chOff[0] = 0;
        for (int i = 0; i < 12; i++) pp.chOff[i+1] = pp.chOff[i] + counts[i];
        for (int i = 0; i < 13; i++) pwo[i] = pp.chOff[i];
        auto setS = [&](int s, int w, int ns, int d0,int s0,int l0, int d1,int s1,int l1) {
            pp.wsel[s]=w; pp.nseg[s]=ns;
            pp.d0[s]=d0; pp.s0[s]=s0; pp.l0[s]=l0;
            pp.d1[s]=d1; pp.s1[s]=s1; pp.l1[s]=l1;
        };
        setS(0, 0, 2, 0,0,128,   128,128,4);   // g1r: nf_r + xorg_r
        setS(1, 0, 2, 0,132,128, 128,260,4);   // g1c: nf_c + xorg_c
        setS(2, 0, 2, 0,264,128, 128,392,4);   // g1e: ef + eam
        setS(3, 1, 1, 0,0,128,   0,0,0);       // g2r
        setS(4, 1, 1, 0,128,128, 0,0,0);       // g2c
        setS(5, 1, 2, 0,260,128, 128,256,4);   // g2e: e1 + eam
        setS(6, 2, 1, 0,0,256,   0,0,0);       // g3r
        setS(7, 2, 1, 0,256,256, 0,0,0);       // g3c
        setS(8, 2, 1, 0,512,256, 0,0,0);       // g3e
        setS(9, 3, 1, 0,0,256,   0,0,0);       // g4r
        setS(10,3, 1, 0,256,256, 0,0,0);       // g4c
        setS(11,3, 1, 0,512,256, 0,0,0);       // g4e
        permAll_kernel<<<(76*4096 + 255)/256, 256>>>(pp, PW);
    }

    const int EGRID = (N_EDGES + BM - 1) / BM;
    const int NGRID = (N_NODES + BM - 1) / BM;

    auto node_pair = [&](int slotR, int slotC, const float* t0, int sh0,
                         const float* t1, int sh1, bool t1side) {
        GP p{};
        p.st[0] = { t0, 128, 132, 4, sh0 };
        if (t1side)   { p.st[1] = { t1, 32, 36, 1, 0 };    p.nSt = 2; p.totCh = 5; }
        else if (t1)  { p.st[1] = { t1, 128, 132, 4, sh1 }; p.nSt = 2; p.totCh = 8; }
        else          { p.nSt = 1; p.totCh = 4; }
        p.PW  = PW + (size_t)pwo[slotR]*4096;
        p.PW2 = PW + (size_t)pwo[slotC]*4096;
        p.nRows = N_NODES; p.Yout = Yr; p.Yout2 = Yc;
        gemm_k<<<dim3(NGRID, 2), 256, SMEM_BYTES>>>(p);
    };
    auto edge_gemm = [&](int slot, const float* t0, int sh0, const float* t1, int sh1,
                         bool t1side, const float* bias, float* e_out) {
        GP p{};
        p.st[0] = { t0, 128, 132, 4, sh0 };
        if (t1side) { p.st[1] = { t1, 32, 36, 1, 0 };    p.nSt = 2; p.totCh = 5; }
        else        { p.st[1] = { t1, 128, 132, 4, sh1 }; p.nSt = 2; p.totCh = 8; }
        p.PW = PW + (size_t)pwo[slot]*4096; p.PW2 = p.PW;
        p.bias = bias; p.Yr = Yr; p.Yc = Yc;
        p.e_out = e_out; p.xsum = xsum;
        p.row = row; p.col = col;
        p.nRows = N_EDGES; p.Yout = nullptr; p.Yout2 = nullptr;
        gemm_k<<<EGRID, 256, SMEM_BYTES>>>(p);
    };
    auto upd = [&](float* xout) {
        node_update<<<(N_NODES*128 + 255)/256, 256>>>(xsum, cnt, xout, N_NODES*128);
    };

    // Layer 1
    node_pair(0, 1, node_feat, 0, nside, 0, true);
    edge_gemm(2, edge_feat, 0, side, 0, true, b1, e1);
    upd(x1);
    // Layer 2
    node_pair(3, 4, x1, 2, nullptr, 0, false);
    edge_gemm(5, e1, 2, side, 0, true, b2, e2);
    upd(x2);
    // Layer 3
    node_pair(6, 7, x2, 2, x1, 2, false);
    edge_gemm(8, e2, 2, e1, 2, false, b3, e3);
    upd(x3);
    // Layer 4
    node_pair(9, 10, x3, 2, x2, 2, false);
    edge_gemm(11, e3, 2, e2, 2, false, b4, e4);
    upd(x4);

    lin1_kernel<<<(N_NODES + 255)/256, 256>>>(x4, lin1_w, lin1_b, x_org, out + OFF_X);
    loss_kernel<<<(N_EDGES + 255)/256, 256>>>(gt_q, out + OFF_X, row, col, beta, lossacc);
    finalize_kernel<<<1, 1>>>(lossacc, beta, out);
    outres_kernel<<<(N_EDGES*32 + 255)/256, 256>>>(e4, lin2_w, lin2_b, out);

    (void)in_sizes; (void)n_in; (void)out_size;
}

// round 13
// speedup vs baseline: 1.2740x; 1.0105x over previous
#include <cuda_runtime.h>
#include <math.h>

#define N_NODES 10000
#define N_EDGES 200000

// ---- output offsets (pytree leaf order) ----
#define OFF_X     0
#define OFF_LOSS  40000
#define OFF_BETA  40001
#define OFF_RES   40002
#define OFF_X1    240002
#define OFF_X2    1520002
#define OFF_X3    2800002
#define OFF_X4    4080002
#define OFF_E1    5360002
#define OFF_E2    30960002
#define OFF_E3    56560002
#define OFF_E4    82160002

// ---- scratch ----
__device__ float g_xsum[N_NODES * 128];   // zero-init at load; invariant: zero after each launch
__device__ int   g_cnt[N_NODES];
__device__ float g_loss[1];
__device__ float g_side[N_EDGES * 32];    // [eam(4) | zeros] tf32, edge-major
__device__ float g_nside[N_NODES * 32];   // [xorg(4) | zeros] tf32, node-major
__device__ float g_Yr[N_NODES * 128];
__device__ float g_Yc[N_NODES * 128];
__device__ float g_PW[76 * 4096];         // permuted tf32 weights

__device__ __forceinline__ unsigned f2tf32(float f) {
    unsigned u;
    asm("cvt.rna.tf32.f32 %0, %1;" : "=r"(u) : "f"(f));
    return u;
}
__device__ __forceinline__ float tf32f(float f) { return __uint_as_float(f2tf32(f)); }

__device__ __forceinline__ void red_add_v4(float* p, float4 v) {
    asm volatile("red.global.add.v4.f32 [%0], {%1,%2,%3,%4};"
                 :: "l"(p), "f"(v.x), "f"(v.y), "f"(v.z), "f"(v.w) : "memory");
}

__device__ __forceinline__ void qmul4(float qw,float qx,float qy,float qz,
                                      float rw,float rx,float ry,float rz,
                                      float& ow,float& ox,float& oy,float& oz) {
    ow = qw*rw - qx*rx - qy*ry - qz*rz;
    ox = qw*rx + qx*rw + qy*rz - qz*ry;
    oy = qw*ry - qx*rz + qy*rw + qz*rx;
    oz = qw*rz + qx*ry - qy*rx + qz*rw;
}

// ---------------- small kernels ----------------
__global__ void zero_f(float* p, int n) {
    int i = blockIdx.x * blockDim.x + threadIdx.x;
    if (i < n) p[i] = 0.f;
}
__global__ void zero_i(int* p, int n) {
    int i = blockIdx.x * blockDim.x + threadIdx.x;
    if (i < n) p[i] = 0;
}
__global__ void fill_f(float* p, const float* val, int n) {
    int i = blockIdx.x * blockDim.x + threadIdx.x;
    if (i < n) p[i] = val[0];
}

// side (eam, tf32) + nside (xorg, tf32) + row counts
__global__ void prep_kernel(const float* __restrict__ x_org,
                            const float* __restrict__ edge_attr,
                            const int* __restrict__ row,
                            const int* __restrict__ col,
                            float* __restrict__ side,
                            float* __restrict__ nside,
                            int* __restrict__ cnt) {
    int e = blockIdx.x * blockDim.x + threadIdx.x;
    if (e < N_NODES) {
        float* s = nside + (size_t)e * 32;
        s[0]=tf32f(x_org[e*4+0]); s[1]=tf32f(x_org[e*4+1]);
        s[2]=tf32f(x_org[e*4+2]); s[3]=tf32f(x_org[e*4+3]);
#pragma unroll
        for (int i = 4; i < 32; i++) s[i] = 0.f;
    }
    if (e >= N_EDGES) return;
    int r = row[e], c = col[e];
    float cw = x_org[c*4+0], cx = -x_org[c*4+1], cy = -x_org[c*4+2], cz = -x_org[c*4+3];
    float aw = edge_attr[e*4+0], ax = edge_attr[e*4+1], ay = edge_attr[e*4+2], az = edge_attr[e*4+3];
    float tw,tx,ty,tz;
    qmul4(cw,cx,cy,cz, aw,ax,ay,az, tw,tx,ty,tz);
    float rw = x_org[r*4+0], rx = x_org[r*4+1], ry = x_org[r*4+2], rz = x_org[r*4+3];
    float ow,ox,oy,oz;
    qmul4(tw,tx,ty,tz, rw,rx,ry,rz, ow,ox,oy,oz);
    float* s = side + (size_t)e * 32;
    s[0]=tf32f(ow); s[1]=tf32f(ox); s[2]=tf32f(oy); s[3]=tf32f(oz);
#pragma unroll
    for (int i = 4; i < 32; i++) s[i] = 0.f;
    atomicAdd(&cnt[r], 1);
}

// ---- single-launch weight permuter for all 12 sub-GEMMs (76 chunks) ----
struct PermAll {
    const float* W[4];
    int chOff[13];
    int wsel[12];
    int nseg[12];
    int d0[12], s0[12], l0[12];
    int d1[12], s1[12], l1[12];
};
__global__ void permAll_kernel(const __grid_constant__ PermAll pp, float* __restrict__ PW) {
    int o = blockIdx.x * blockDim.x + threadIdx.x;
    if (o >= 76 * 4096) return;
    int gch = o >> 12, r = o & 4095;
    int slot = 0;
#pragma unroll
    for (int s = 0; s < 12; s++) if (gch >= pp.chOff[s+1]) slot = s + 1;
    int ch = gch - pp.chOff[slot];
    int wn = r >> 10, r2 = r & 1023;
    int ks = r2 >> 8, r3 = r2 & 255;
    int q  = r3 >> 7, r4 = r3 & 127;
    int lane = r4 >> 2, elem = r4 & 3;
    int g = lane >> 2, tg = lane & 3;
    int kp = ch*32 + ks*8 + tg + (elem & 1)*4;
    int n  = wn*32 + (2*q + (elem >> 1))*8 + g;
    const float* W = pp.W[pp.wsel[slot]];
    float v = 0.f;
    if (kp >= pp.d0[slot] && kp < pp.d0[slot] + pp.l0[slot])
        v = tf32f(W[(size_t)(pp.s0[slot] + kp - pp.d0[slot]) * 128 + n]);
    else if (pp.nseg[slot] > 1 && kp >= pp.d1[slot] && kp < pp.d1[slot] + pp.l1[slot])
        v = tf32f(W[(size_t)(pp.s1[slot] + kp - pp.d1[slot]) * 128 + n]);
    PW[o] = v;
}

// ---------------- contiguous-A tf32 GEMM (256 threads, 2 CTAs/SM) ----------------
struct Stage { const float* tab; int widthF; int strideF; int nCh; int shiftF; };
struct GP {
    Stage st[2]; int nSt; int totCh;
    const float* PW;  const float* PW2;
    const float* bias;
    const float* Yr; const float* Yc;
    float* e_out; float* xsum;
    const int* row; const int* col;
    int nRows;
    float* Yout; float* Yout2;
    const float* w2;     // lin2_w (layer-4 edge GEMM only)
    float* ores;         // out_res accumulator (pre-filled with lin2_b), or nullptr
};

#define BM 128
#define A_BUF_F 16896     // 128 * 132 (single buffer, reused across stages)
#define B_BUF_F 4096
#define SMEM_FLOATS (A_BUF_F + 2*B_BUF_F)
#define SMEM_BYTES  (SMEM_FLOATS*4 + 32)

__device__ __forceinline__ void bulk_g2s(unsigned dst, const float* src, unsigned bytes,
                                         unsigned mbar) {
    asm volatile(
        "cp.async.bulk.shared::cluster.global.mbarrier::complete_tx::bytes [%0], [%1], %2, [%3];"
        :: "r"(dst), "l"(src), "r"(bytes), "r"(mbar) : "memory");
}
__device__ __forceinline__ void mbar_init(unsigned mbar, unsigned cnt) {
    asm volatile("mbarrier.init.shared.b64 [%0], %1;" :: "r"(mbar), "r"(cnt) : "memory");
}
__device__ __forceinline__ void mbar_expect(unsigned mbar, unsigned bytes) {
    asm volatile("mbarrier.arrive.expect_tx.shared.b64 _, [%0], %1;"
                 :: "r"(mbar), "r"(bytes) : "memory");
}
__device__ __forceinline__ void mbar_wait(unsigned mbar, unsigned parity) {
    asm volatile(
        "{\n\t.reg .pred P;\n\t"
        "WAIT_%=:\n\t"
        "mbarrier.try_wait.parity.acquire.cta.shared::cta.b64 P, [%0], %1, 0x989680;\n\t"
        "@P bra.uni DONE_%=;\n\t"
        "bra.uni WAIT_%=;\n\t"
        "DONE_%=:\n\t}"
        :: "r"(mbar), "r"(parity) : "memory");
}

__global__ void __launch_bounds__(256, 2)
gemm_k(const __grid_constant__ GP p) {
    extern __shared__ __align__(16) float smem[];
    float* Abuf = smem;
    float* Bbuf[2] = { smem + A_BUF_F, smem + A_BUF_F + B_BUF_F };
    unsigned mbase = (unsigned)__cvta_generic_to_shared(smem + SMEM_FLOATS);
    unsigned mbA = mbase;
    unsigned mbB[2] = { mbase + 8, mbase + 16 };
    unsigned AbufU = (unsigned)__cvta_generic_to_shared(Abuf);
    unsigned BbufU[2] = { (unsigned)__cvta_generic_to_shared(Bbuf[0]),
                          (unsigned)__cvta_generic_to_shared(Bbuf[1]) };

    const float* PW = blockIdx.y ? p.PW2 : p.PW;
    float* Yout = blockIdx.y ? p.Yout2 : p.Yout;

    int tid = threadIdx.x;
    int lane = tid & 31, wrp = tid >> 5;
    int r_base = blockIdx.x * BM;

    if (tid == 0) {
        mbar_init(mbA, 1);
        mbar_init(mbB[0], 1); mbar_init(mbB[1], 1);
    }
    __syncthreads();

    int wm = wrp & 3, wn = wrp >> 2;      // wn in {0,1}
    int m0 = wm * 32, nb = wn * 64;
    int g = lane >> 2, tg = lane & 3;

    float acc[2][8][4];
#pragma unroll
    for (int mt = 0; mt < 2; mt++)
#pragma unroll
        for (int j = 0; j < 8; j++)
#pragma unroll
            for (int c = 0; c < 4; c++) acc[mt][j][c] = 0.f;

    auto issueA = [&](int s) {
        if (tid < 128) {
            Stage st = p.st[s];
            int idx = min(r_base + tid, p.nRows - 1);
            const float* src = st.tab + (size_t)idx * st.widthF - st.shiftF;
            unsigned bytes = (unsigned)(st.widthF + (st.shiftF ? 4 : 0)) * 4u;
            bulk_g2s(AbufU + (unsigned)(tid * st.strideF * 4), src, bytes, mbA);
            if (tid == 0) mbar_expect(mbA, 128u * bytes);
        }
    };
    auto issueB = [&](int gc) {
        if (tid == 0) {
            bulk_g2s(BbufU[gc & 1], PW + (size_t)gc * 4096, 16384, mbB[gc & 1]);
            mbar_expect(mbB[gc & 1], 16384);
        }
    };
    auto compute = [&](int strideF, int kShift, int kkBase, const float* Bs) {
#pragma unroll
        for (int ks = 0; ks < 4; ks++) {
            int kk = kkBase + ks * 8 + kShift;
            unsigned a[2][4];
#pragma unroll
            for (int mt = 0; mt < 2; mt++) {
                int r = m0 + mt * 16;
                a[mt][0] = f2tf32(Abuf[(r + g    ) * strideF + kk + tg    ]);
                a[mt][1] = f2tf32(Abuf[(r + g + 8) * strideF + kk + tg    ]);
                a[mt][2] = f2tf32(Abuf[(r + g    ) * strideF + kk + tg + 4]);
                a[mt][3] = f2tf32(Abuf[(r + g + 8) * strideF + kk + tg + 4]);
            }
#pragma unroll
            for (int sub = 0; sub < 2; sub++) {
                int wnG = wn * 2 + sub;
#pragma unroll
                for (int q = 0; q < 2; q++) {
                    float4 bv = *reinterpret_cast<const float4*>(
                        &Bs[(((wnG*4 + ks)*2 + q)*32 + lane)*4]);
                    unsigned b00 = __float_as_uint(bv.x), b01 = __float_as_uint(bv.y);
                    unsigned b10 = __float_as_uint(bv.z), b11 = __float_as_uint(bv.w);
                    int j0 = sub*4 + 2*q, j1 = j0 + 1;
#pragma unroll
                    for (int mt = 0; mt < 2; mt++) {
                        asm volatile(
                            "mma.sync.aligned.m16n8k8.row.col.f32.tf32.tf32.f32 "
                            "{%0,%1,%2,%3}, {%4,%5,%6,%7}, {%8,%9}, {%0,%1,%2,%3};"
                            : "+f"(acc[mt][j0][0]), "+f"(acc[mt][j0][1]),
                              "+f"(acc[mt][j0][2]), "+f"(acc[mt][j0][3])
                            : "r"(a[mt][0]), "r"(a[mt][1]), "r"(a[mt][2]), "r"(a[mt][3]),
                              "r"(b00), "r"(b01));
                        asm volatile(
                            "mma.sync.aligned.m16n8k8.row.col.f32.tf32.tf32.f32 "
                            "{%0,%1,%2,%3}, {%4,%5,%6,%7}, {%8,%9}, {%0,%1,%2,%3};"
                            : "+f"(acc[mt][j1][0]), "+f"(acc[mt][j1][1]),
                              "+f"(acc[mt][j1][2]), "+f"(acc[mt][j1][3])
                            : "r"(a[mt][0]), "r"(a[mt][1]), "r"(a[mt][2]), "r"(a[mt][3]),
                              "r"(b10), "r"(b11));
                    }
                }
            }
        }
    };

    issueA(0);
    issueB(0);
    if (p.totCh > 1) issueB(1);

    int gc = 0;
    for (int s = 0; s < p.nSt; s++) {
        mbar_wait(mbA, s & 1);
        int strideF = p.st[s].strideF;
        int kShift = p.st[s].shiftF;
        int nc = p.st[s].nCh;
        for (int c = 0; c < nc; c++, gc++) {
            mbar_wait(mbB[gc & 1], (gc >> 1) & 1);
            compute(strideF, kShift, c * 32, Bbuf[gc & 1]);
            __syncthreads();
            if (gc + 2 < p.totCh) issueB(gc + 2);
            if (c == nc - 1 && s + 1 < p.nSt) issueA(s + 1);
        }
    }

    // ---- epilogue: lane-paired float4 path ----
    bool isEven = ((tg & 1) == 0);
    int tbase = nb + (isEven ? tg : (tg - 1)) * 2;

    if (Yout) {
#pragma unroll
        for (int mt = 0; mt < 2; mt++) {
            int nA = r_base + m0 + mt * 16 + g;
            int nS = isEven ? nA : (nA + 8);
            bool vS = nS < p.nRows;
#pragma unroll
            for (int j = 0; j < 8; j++) {
                float a0 = acc[mt][j][0], a1 = acc[mt][j][1];
                float b0 = acc[mt][j][2], b1 = acc[mt][j][3];
                float na0 = __shfl_xor_sync(0xFFFFFFFFu, a0, 1);
                float na1 = __shfl_xor_sync(0xFFFFFFFFu, a1, 1);
                float nb0 = __shfl_xor_sync(0xFFFFFFFFu, b0, 1);
                float nb1 = __shfl_xor_sync(0xFFFFFFFFu, b1, 1);
                float4 a4 = isEven ? make_float4(a0, a1, na0, na1)
                                   : make_float4(nb0, nb1, b0, b1);
                if (vS)
                    *reinterpret_cast<float4*>(&Yout[(size_t)nS*128 + tbase + j*8]) = a4;
            }
        }
    } else {
#pragma unroll
        for (int mt = 0; mt < 2; mt++) {
            int eA = r_base + m0 + mt * 16 + g;
            int eS = isEven ? eA : (eA + 8);
            bool vS = eS < N_EDGES;
            int rS = vS ? p.row[eS] : 0;
            int cS = vS ? p.col[eS] : 0;
            float lsum = 0.f;
#pragma unroll
            for (int j = 0; j < 8; j++) {
                float a0 = acc[mt][j][0], a1 = acc[mt][j][1];
                float b0 = acc[mt][j][2], b1 = acc[mt][j][3];
                float na0 = __shfl_xor_sync(0xFFFFFFFFu, a0, 1);
                float na1 = __shfl_xor_sync(0xFFFFFFFFu, a1, 1);
                float nb0 = __shfl_xor_sync(0xFFFFFFFFu, b0, 1);
                float nb1 = __shfl_xor_sync(0xFFFFFFFFu, b1, 1);
                if (vS) {
                    float4 a4 = isEven ? make_float4(a0, a1, na0, na1)
                                       : make_float4(nb0, nb1, b0, b1);
                    int n4 = tbase + j*8;
                    float4 bias4 = *reinterpret_cast<const float4*>(&p.bias[n4]);
                    float4 yr = *reinterpret_cast<const float4*>(&p.Yr[(size_t)rS*128 + n4]);
                    float4 yc = *reinterpret_cast<const float4*>(&p.Yc[(size_t)cS*128 + n4]);
                    float4 m4 = make_float4(a4.x + bias4.x + yr.x + yc.x,
                                            a4.y + bias4.y + yr.y + yc.y,
                                            a4.z + bias4.z + yr.z + yc.z,
                                            a4.w + bias4.w + yr.w + yc.w);
                    float o0 = fmaxf(m4.x, 0.f), o1 = fmaxf(m4.y, 0.f);
                    float o2 = fmaxf(m4.z, 0.f), o3 = fmaxf(m4.w, 0.f);
                    *reinterpret_cast<float2*>(&p.e_out[(size_t)eS*128 + n4]) =
                        make_float2(o0, o1);
                    *reinterpret_cast<float2*>(&p.e_out[(size_t)eS*128 + n4 + 2]) =
                        make_float2(o2, o3);
                    red_add_v4(&p.xsum[(size_t)rS*128 + n4], m4);
                    if (p.ores) {
                        float4 w4 = *reinterpret_cast<const float4*>(&p.w2[n4]);
                        lsum = fmaf(o0, w4.x, fmaf(o1, w4.y,
                               fmaf(o2, w4.z, fmaf(o3, w4.w, lsum))));
                    }
                }
            }
            if (p.ores && vS) atomicAdd(&p.ores[eS], lsum);
        }
    }
}

// x_next = relu(xsum / max(cnt,1)); resets xsum
__global__ void node_update(float* __restrict__ xsum,
                            const int* __restrict__ cnt,
                            float* __restrict__ xout, int n_elems) {
    int i = blockIdx.x * blockDim.x + threadIdx.x;
    if (i >= n_elems) return;
    int node = i >> 7;
    float c = (float)max(cnt[node], 1);
    float v = xsum[i];
    xsum[i] = 0.f;
    xout[i] = fmaxf(v / c, 0.f);
}

__global__ void lin1_kernel(const float* __restrict__ x4,
                            const float* __restrict__ w,
                            const float* __restrict__ bb,
                            const float* __restrict__ x_org,
                            float* __restrict__ xout) {
    int n = blockIdx.x * blockDim.x + threadIdx.x;
    if (n >= N_NODES) return;
    float q0 = bb[0], q1 = bb[1], q2 = bb[2], q3 = bb[3];
    for (int k = 0; k < 128; k++) {
        float v = x4[(size_t)n * 128 + k];
        q0 = fmaf(v, w[k*4+0], q0);
        q1 = fmaf(v, w[k*4+1], q1);
        q2 = fmaf(v, w[k*4+2], q2);
        q3 = fmaf(v, w[k*4+3], q3);
    }
    float rw = x_org[n*4+0], rx = x_org[n*4+1], ry = x_org[n*4+2], rz = x_org[n*4+3];
    float ow,ox,oy,oz;
    qmul4(q0,q1,q2,q3, rw,rx,ry,rz, ow,ox,oy,oz);
    float nn = sqrtf(ow*ow + ox*ox + oy*oy + oz*oz);
    nn = fmaxf(nn, 1e-12f);
    xout[n*4+0] = ow/nn; xout[n*4+1] = ox/nn; xout[n*4+2] = oy/nn; xout[n*4+3] = oz/nn;
}

__global__ void loss_kernel(const float* __restrict__ gt,
                            const float* __restrict__ x,
                            const int* __restrict__ row,
                            const int* __restrict__ col,
                            const float* __restrict__ beta_p,
                            float* __restrict__ loss_acc) {
    int e = blockIdx.x * blockDim.x + threadIdx.x;
    float local = 0.f;
    if (e < N_EDGES) {
        int r = row[e], c = col[e];
        float aw = gt[c*4+0], ax = gt[c*4+1], ay = gt[c*4+2], az = gt[c*4+3];
        float bw = gt[r*4+0], bx = -gt[r*4+1], by = -gt[r*4+2], bz = -gt[r*4+3];
        float gw,gx,gy,gz;
        qmul4(aw,ax,ay,az, bw,bx,by,bz, gw,gx,gy,gz);
        float cw2 = x[c*4+0], cx2 = x[c*4+1], cy2 = x[c*4+2], cz2 = x[c*4+3];
        float dw = x[r*4+0], dx = -x[r*4+1], dy = -x[r*4+2], dz = -x[r*4+3];
        float xw,xx,xy,xz;
        qmul4(cw2,cx2,cy2,cz2, dw,dx,dy,dz, xw,xx,xy,xz);
        float lw,lx,ly,lz;
        qmul4(gw,-gx,-gy,-gz, xw,xx,xy,xz, lw,lx,ly,lz);
        float nn = sqrtf(lw*lw + lx*lx + ly*ly + lz*lz);
        nn = fmaxf(nn, 1e-12f);
        lw /= nn; lx /= nn; ly /= nn; lz /= nn;
        float beta = beta_p[0];
        float d[4] = {fabsf(lw - 1.f), fabsf(lx), fabsf(ly), fabsf(lz)};
#pragma unroll
        for (int i = 0; i < 4; i++) {
            float v = d[i];
            local += (v < beta) ? (0.5f * v * v / beta) : (v - 0.5f * beta);
        }
    }
    __shared__ float sm[256];
    sm[threadIdx.x] = local;
    __syncthreads();
    for (int s = 128; s > 0; s >>= 1) {
        if (threadIdx.x < s) sm[threadIdx.x] += sm[threadIdx.x + s];
        __syncthreads();
    }
    if (threadIdx.x == 0) atomicAdd(loss_acc, sm[0]);
}

__global__ void finalize_kernel(const float* __restrict__ loss_acc,
                                const float* __restrict__ beta_p,
                                float* __restrict__ out) {
    out[OFF_LOSS] = loss_acc[0] / (float)(N_EDGES * 4);
    out[OFF_BETA] = beta_p[0];
}

// ---------------- host ----------------
extern "C" void kernel_launch(void* const* d_in, const int* in_sizes, int n_in,
                              void* d_out, int out_size) {
    const float* x_org     = (const float*)d_in[0];
    const float* edge_attr = (const float*)d_in[1];
    const float* gt_q      = (const float*)d_in[2];
    const float* beta      = (const float*)d_in[3];
    const float* node_feat = (const float*)d_in[4];
    const float* edge_feat = (const float*)d_in[5];
    const float* W1 = (const float*)d_in[6];
    const float* b1 = (const float*)d_in[7];
    const float* W2 = (const float*)d_in[8];
    const float* b2 = (const float*)d_in[9];
    const float* W3 = (const float*)d_in[10];
    const float* b3 = (const float*)d_in[11];
    const float* W4 = (const float*)d_in[12];
    const float* b4 = (const float*)d_in[13];
    const float* lin1_w = (const float*)d_in[14];
    const float* lin1_b = (const float*)d_in[15];
    const float* lin2_w = (const float*)d_in[16];
    const float* lin2_b = (const float*)d_in[17];
    const int* ei = (const int*)d_in[18];
    const int* row = ei;
    const int* col = ei + N_EDGES;

    float* out = (float*)d_out;
    float* x1 = out + OFF_X1;
    float* x2 = out + OFF_X2;
    float* x3 = out + OFF_X3;
    float* x4 = out + OFF_X4;
    float* e1 = out + OFF_E1;
    float* e2 = out + OFF_E2;
    float* e3 = out + OFF_E3;
    float* e4 = out + OFF_E4;

    float *xsum, *lossacc, *side, *nside, *PW, *Yr, *Yc;
    int* cnt;
    cudaGetSymbolAddress((void**)&xsum, g_xsum);
    cudaGetSymbolAddress((void**)&lossacc, g_loss);
    cudaGetSymbolAddress((void**)&cnt, g_cnt);
    cudaGetSymbolAddress((void**)&side, g_side);
    cudaGetSymbolAddress((void**)&nside, g_nside);
    cudaGetSymbolAddress((void**)&PW, g_PW);
    cudaGetSymbolAddress((void**)&Yr, g_Yr);
    cudaGetSymbolAddress((void**)&Yc, g_Yc);

    cudaFuncSetAttribute(gemm_k, cudaFuncAttributeMaxDynamicSharedMemorySize, SMEM_BYTES);

    zero_i<<<(N_NODES + 255)/256, 256>>>(cnt, N_NODES);
    zero_f<<<1, 32>>>(lossacc, 1);
    fill_f<<<(N_EDGES + 255)/256, 256>>>(out + OFF_RES, lin2_b, N_EDGES);
    prep_kernel<<<(N_EDGES + 255)/256, 256>>>(x_org, edge_attr, row, col, side, nside, cnt);

    // ---- one-shot weight permute (12 slots, 76 chunks) ----
    int pwo[13];
    {
        PermAll pp;
        pp.W[0]=W1; pp.W[1]=W2; pp.W[2]=W3; pp.W[3]=W4;
        int counts[12] = {5,5,5,4,4,5,8,8,8,8,8,8};
        pp.chOff[0] = 0;
        for (int i = 0; i < 12; i++) pp.chOff[i+1] = pp.chOff[i] + counts[i];
        for (int i = 0; i < 13; i++) pwo[i] = pp.chOff[i];
        auto setS = [&](int s, int w, int ns, int d0,int s0,int l0, int d1,int s1,int l1) {
            pp.wsel[s]=w; pp.nseg[s]=ns;
            pp.d0[s]=d0; pp.s0[s]=s0; pp.l0[s]=l0;
            pp.d1[s]=d1; pp.s1[s]=s1; pp.l1[s]=l1;
        };
        setS(0, 0, 2, 0,0,128,   128,128,4);   // g1r: nf_r + xorg_r
        setS(1, 0, 2, 0,132,128, 128,260,4);   // g1c: nf_c + xorg_c
        setS(2, 0, 2, 0,264,128, 128,392,4);   // g1e: ef + eam
        setS(3, 1, 1, 0,0,128,   0,0,0);       // g2r
        setS(4, 1, 1, 0,128,128, 0,0,0);       // g2c
        setS(5, 1, 2, 0,260,128, 128,256,4);   // g2e: e1 + eam
        setS(6, 2, 1, 0,0,256,   0,0,0);       // g3r
        setS(7, 2, 1, 0,256,256, 0,0,0);       // g3c
        setS(8, 2, 1, 0,512,256, 0,0,0);       // g3e
        setS(9, 3, 1, 0,0,256,   0,0,0);       // g4r
        setS(10,3, 1, 0,256,256, 0,0,0);       // g4c
        setS(11,3, 1, 0,512,256, 0,0,0);       // g4e
        permAll_kernel<<<(76*4096 + 255)/256, 256>>>(pp, PW);
    }

    const int EGRID = (N_EDGES + BM - 1) / BM;
    const int NGRID = (N_NODES + BM - 1) / BM;

    auto node_pair = [&](int slotR, int slotC, const float* t0, int sh0,
                         const float* t1, int sh1, bool t1side) {
        GP p{};
        p.st[0] = { t0, 128, 132, 4, sh0 };
        if (t1side)   { p.st[1] = { t1, 32, 36, 1, 0 };    p.nSt = 2; p.totCh = 5; }
        else if (t1)  { p.st[1] = { t1, 128, 132, 4, sh1 }; p.nSt = 2; p.totCh = 8; }
        else          { p.nSt = 1; p.totCh = 4; }
        p.PW  = PW + (size_t)pwo[slotR]*4096;
        p.PW2 = PW + (size_t)pwo[slotC]*4096;
        p.nRows = N_NODES; p.Yout = Yr; p.Yout2 = Yc;
        gemm_k<<<dim3(NGRID, 2), 256, SMEM_BYTES>>>(p);
    };
    auto edge_gemm = [&](int slot, const float* t0, int sh0, const float* t1, int sh1,
                         bool t1side, const float* bias, float* e_out,
                         const float* w2, float* ores) {
        GP p{};
        p.st[0] = { t0, 128, 132, 4, sh0 };
        if (t1side) { p.st[1] = { t1, 32, 36, 1, 0 };    p.nSt = 2; p.totCh = 5; }
        else        { p.st[1] = { t1, 128, 132, 4, sh1 }; p.nSt = 2; p.totCh = 8; }
        p.PW = PW + (size_t)pwo[slot]*4096; p.PW2 = p.PW;
        p.bias = bias; p.Yr = Yr; p.Yc = Yc;
        p.e_out = e_out; p.xsum = xsum;
        p.row = row; p.col = col;
        p.nRows = N_EDGES; p.Yout = nullptr; p.Yout2 = nullptr;
        p.w2 = w2; p.ores = ores;
        gemm_k<<<EGRID, 256, SMEM_BYTES>>>(p);
    };
    auto upd = [&](float* xout) {
        node_update<<<(N_NODES*128 + 255)/256, 256>>>(xsum, cnt, xout, N_NODES*128);
    };

    // Layer 1
    node_pair(0, 1, node_feat, 0, nside, 0, true);
    edge_gemm(2, edge_feat, 0, side, 0, true, b1, e1, nullptr, nullptr);
    upd(x1);
    // Layer 2
    node_pair(3, 4, x1, 2, nullptr, 0, false);
    edge_gemm(5, e1, 2, side, 0, true, b2, e2, nullptr, nullptr);
    upd(x2);
    // Layer 3
    node_pair(6, 7, x2, 2, x1, 2, false);
    edge_gemm(8, e2, 2, e1, 2, false, b3, e3, nullptr, nullptr);
    upd(x3);
    // Layer 4 (fused out_res = relu(m) @ lin2_w + lin2_b)
    node_pair(9, 10, x3, 2, x2, 2, false);
    edge_gemm(11, e3, 2, e2, 2, false, b4, e4, lin2_w, out + OFF_RES);
    upd(x4);

    lin1_kernel<<<(N_NODES + 255)/256, 256>>>(x4, lin1_w, lin1_b, x_org, out + OFF_X);
    loss_kernel<<<(N_EDGES + 255)/256, 256>>>(gt_q, out + OFF_X, row, col, beta, lossacc);
    finalize_kernel<<<1, 1>>>(lossacc, beta, out);

    (void)in_sizes; (void)n_in; (void)out_size;
}

// round 15
// speedup vs baseline: 1.3343x; 1.0473x over previous
#include <cuda_runtime.h>
#include <math.h>

#define N_NODES 10000
#define N_EDGES 200000

// ---- output offsets (pytree leaf order) ----
#define OFF_X     0
#define OFF_LOSS  40000
#define OFF_BETA  40001
#define OFF_RES   40002
#define OFF_X1    240002
#define OFF_X2    1520002
#define OFF_X3    2800002
#define OFF_X4    4080002
#define OFF_E1    5360002
#define OFF_E2    30960002
#define OFF_E3    56560002
#define OFF_E4    82160002

// ---- scratch ----
__device__ float g_xsum[N_NODES * 128];   // zero-init at load; invariant: zero after each launch
__device__ int   g_cnt[N_NODES];
__device__ float g_loss[1];
// zero-init at load; only floats [0,4) of each 32-float row are ever written,
// the remaining 28 stay zero forever (relied upon by the GEMM side-chunk).
__device__ float g_side[N_EDGES * 32];
__device__ float g_nside[N_NODES * 32];
__device__ float g_Yr[N_NODES * 128];
__device__ float g_Yc[N_NODES * 128];
__device__ float g_PW[76 * 4096];         // permuted tf32 weights

__device__ __forceinline__ unsigned f2tf32(float f) {
    unsigned u;
    asm("cvt.rna.tf32.f32 %0, %1;" : "=r"(u) : "f"(f));
    return u;
}
__device__ __forceinline__ float tf32f(float f) { return __uint_as_float(f2tf32(f)); }

__device__ __forceinline__ void red_add_v4(float* p, float4 v) {
    asm volatile("red.global.add.v4.f32 [%0], {%1,%2,%3,%4};"
                 :: "l"(p), "f"(v.x), "f"(v.y), "f"(v.z), "f"(v.w) : "memory");
}

__device__ __forceinline__ void qmul4(float qw,float qx,float qy,float qz,
                                      float rw,float rx,float ry,float rz,
                                      float& ow,float& ox,float& oy,float& oz) {
    ow = qw*rw - qx*rx - qy*ry - qz*rz;
    ox = qw*rx + qx*rw + qy*rz - qz*ry;
    oy = qw*ry - qx*rz + qy*rw + qz*rx;
    oz = qw*rz + qx*ry - qy*rx + qz*rw;
}

// ---------------- small kernels ----------------
__global__ void zero_f(float* p, int n) {
    int i = blockIdx.x * blockDim.x + threadIdx.x;
    if (i < n) p[i] = 0.f;
}
__global__ void zero_i(int* p, int n) {
    int i = blockIdx.x * blockDim.x + threadIdx.x;
    if (i < n) p[i] = 0;
}
__global__ void fill_f(float* p, const float* val, int n) {
    int i = blockIdx.x * blockDim.x + threadIdx.x;
    if (i < n) p[i] = val[0];
}

// side (eam, tf32) + nside (xorg, tf32) + row counts — vectorized, no zero stores
__global__ void prep_kernel(const float* __restrict__ x_org,
                            const float* __restrict__ edge_attr,
                            const int* __restrict__ row,
                            const int* __restrict__ col,
                            float* __restrict__ side,
                            float* __restrict__ nside,
                            int* __restrict__ cnt) {
    int e = blockIdx.x * blockDim.x + threadIdx.x;
    const float4* x4p = reinterpret_cast<const float4*>(x_org);
    if (e < N_NODES) {
        float4 q = x4p[e];
        *reinterpret_cast<float4*>(&nside[(size_t)e * 32]) =
            make_float4(tf32f(q.x), tf32f(q.y), tf32f(q.z), tf32f(q.w));
    }
    if (e >= N_EDGES) return;
    int r = row[e], c = col[e];
    float4 qc = x4p[c];
    float4 qa = reinterpret_cast<const float4*>(edge_attr)[e];
    float4 qr = x4p[r];
    float tw,tx,ty,tz;
    qmul4(qc.x, -qc.y, -qc.z, -qc.w, qa.x, qa.y, qa.z, qa.w, tw,tx,ty,tz);
    float ow,ox,oy,oz;
    qmul4(tw,tx,ty,tz, qr.x, qr.y, qr.z, qr.w, ow,ox,oy,oz);
    *reinterpret_cast<float4*>(&side[(size_t)e * 32]) =
        make_float4(tf32f(ow), tf32f(ox), tf32f(oy), tf32f(oz));
    atomicAdd(&cnt[r], 1);
}

// ---- single-launch weight permuter for all 12 sub-GEMMs (76 chunks) ----
struct PermAll {
    const float* W[4];
    int chOff[13];
    int wsel[12];
    int nseg[12];
    int d0[12], s0[12], l0[12];
    int d1[12], s1[12], l1[12];
};
__global__ void permAll_kernel(const __grid_constant__ PermAll pp, float* __restrict__ PW) {
    int o = blockIdx.x * blockDim.x + threadIdx.x;
    if (o >= 76 * 4096) return;
    int gch = o >> 12, r = o & 4095;
    int slot = 0;
#pragma unroll
    for (int s = 0; s < 12; s++) if (gch >= pp.chOff[s+1]) slot = s + 1;
    int ch = gch - pp.chOff[slot];
    int wn = r >> 10, r2 = r & 1023;
    int ks = r2 >> 8, r3 = r2 & 255;
    int q  = r3 >> 7, r4 = r3 & 127;
    int lane = r4 >> 2, elem = r4 & 3;
    int g = lane >> 2, tg = lane & 3;
    int kp = ch*32 + ks*8 + tg + (elem & 1)*4;
    int n  = wn*32 + (2*q + (elem >> 1))*8 + g;
    const float* W = pp.W[pp.wsel[slot]];
    float v = 0.f;
    if (kp >= pp.d0[slot] && kp < pp.d0[slot] + pp.l0[slot])
        v = tf32f(W[(size_t)(pp.s0[slot] + kp - pp.d0[slot]) * 128 + n]);
    else if (pp.nseg[slot] > 1 && kp >= pp.d1[slot] && kp < pp.d1[slot] + pp.l1[slot])
        v = tf32f(W[(size_t)(pp.s1[slot] + kp - pp.d1[slot]) * 128 + n]);
    PW[o] = v;
}

// ---------------- contiguous-A tf32 GEMM (256 threads, 2 CTAs/SM) ----------------
struct Stage { const float* tab; int widthF; int strideF; int nCh; int shiftF; };
struct GP {
    Stage st[2]; int nSt; int totCh;
    const float* PW;  const float* PW2;
    const float* bias;
    const float* Yr; const float* Yc;
    float* e_out; float* xsum;
    const int* row; const int* col;
    int nRows;
    float* Yout; float* Yout2;
    const float* w2;     // lin2_w (layer-4 edge GEMM only)
    float* ores;         // out_res accumulator (pre-filled with lin2_b), or nullptr
};

#define BM 128
#define A_BUF_F 16896     // 128 * 132 (single buffer, reused across stages)
#define B_BUF_F 4096
#define SMEM_FLOATS (A_BUF_F + 2*B_BUF_F)
#define SMEM_BYTES  (SMEM_FLOATS*4 + 32)

__device__ __forceinline__ void bulk_g2s(unsigned dst, const float* src, unsigned bytes,
                                         unsigned mbar) {
    asm volatile(
        "cp.async.bulk.shared::cluster.global.mbarrier::complete_tx::bytes [%0], [%1], %2, [%3];"
        :: "r"(dst), "l"(src), "r"(bytes), "r"(mbar) : "memory");
}
__device__ __forceinline__ void mbar_init(unsigned mbar, unsigned cnt) {
    asm volatile("mbarrier.init.shared.b64 [%0], %1;" :: "r"(mbar), "r"(cnt) : "memory");
}
__device__ __forceinline__ void mbar_expect(unsigned mbar, unsigned bytes) {
    asm volatile("mbarrier.arrive.expect_tx.shared.b64 _, [%0], %1;"
                 :: "r"(mbar), "r"(bytes) : "memory");
}
__device__ __forceinline__ void mbar_wait(unsigned mbar, unsigned parity) {
    asm volatile(
        "{\n\t.reg .pred P;\n\t"
        "WAIT_%=:\n\t"
        "mbarrier.try_wait.parity.acquire.cta.shared::cta.b64 P, [%0], %1, 0x989680;\n\t"
        "@P bra.uni DONE_%=;\n\t"
        "bra.uni WAIT_%=;\n\t"
        "DONE_%=:\n\t}"
        :: "r"(mbar), "r"(parity) : "memory");
}

__global__ void __launch_bounds__(256, 2)
gemm_k(const __grid_constant__ GP p) {
    extern __shared__ __align__(16) float smem[];
    float* Abuf = smem;
    float* Bbuf[2] = { smem + A_BUF_F, smem + A_BUF_F + B_BUF_F };
    unsigned mbase = (unsigned)__cvta_generic_to_shared(smem + SMEM_FLOATS);
    unsigned mbA = mbase;
    unsigned mbB[2] = { mbase + 8, mbase + 16 };
    unsigned AbufU = (unsigned)__cvta_generic_to_shared(Abuf);
    unsigned BbufU[2] = { (unsigned)__cvta_generic_to_shared(Bbuf[0]),
                          (unsigned)__cvta_generic_to_shared(Bbuf[1]) };

    const float* PW = blockIdx.y ? p.PW2 : p.PW;
    float* Yout = blockIdx.y ? p.Yout2 : p.Yout;

    int tid = threadIdx.x;
    int lane = tid & 31, wrp = tid >> 5;
    int r_base = blockIdx.x * BM;

    if (tid == 0) {
        mbar_init(mbA, 1);
        mbar_init(mbB[0], 1); mbar_init(mbB[1], 1);
    }
    __syncthreads();

    int wm = wrp & 3, wn = wrp >> 2;      // wn in {0,1}
    int m0 = wm * 32, nb = wn * 64;
    int g = lane >> 2, tg = lane & 3;

    float acc[2][8][4];
#pragma unroll
    for (int mt = 0; mt < 2; mt++)
#pragma unroll
        for (int j = 0; j < 8; j++)
#pragma unroll
            for (int c = 0; c < 4; c++) acc[mt][j][c] = 0.f;

    auto issueA = [&](int s) {
        if (tid < 128) {
            Stage st = p.st[s];
            int idx = min(r_base + tid, p.nRows - 1);
            const float* src = st.tab + (size_t)idx * st.widthF - st.shiftF;
            unsigned bytes = (unsigned)(st.widthF + (st.shiftF ? 4 : 0)) * 4u;
            bulk_g2s(AbufU + (unsigned)(tid * st.strideF * 4), src, bytes, mbA);
            if (tid == 0) mbar_expect(mbA, 128u * bytes);
        }
    };
    auto issueB = [&](int gc) {
        if (tid == 0) {
            bulk_g2s(BbufU[gc & 1], PW + (size_t)gc * 4096, 16384, mbB[gc & 1]);
            mbar_expect(mbB[gc & 1], 16384);
        }
    };
    auto compute = [&](int strideF, int kShift, int kkBase, const float* Bs) {
#pragma unroll
        for (int ks = 0; ks < 4; ks++) {
            int kk = kkBase + ks * 8 + kShift;
            unsigned a[2][4];
#pragma unroll
            for (int mt = 0; mt < 2; mt++) {
                int r = m0 + mt * 16;
                a[mt][0] = f2tf32(Abuf[(r + g    ) * strideF + kk + tg    ]);
                a[mt][1] = f2tf32(Abuf[(r + g + 8) * strideF + kk + tg    ]);
                a[mt][2] = f2tf32(Abuf[(r + g    ) * strideF + kk + tg + 4]);
                a[mt][3] = f2tf32(Abuf[(r + g + 8) * strideF + kk + tg + 4]);
            }
#pragma unroll
            for (int sub = 0; sub < 2; sub++) {
                int wnG = wn * 2 + sub;
#pragma unroll
                for (int q = 0; q < 2; q++) {
                    float4 bv = *reinterpret_cast<const float4*>(
                        &Bs[(((wnG*4 + ks)*2 + q)*32 + lane)*4]);
                    unsigned b00 = __float_as_uint(bv.x), b01 = __float_as_uint(bv.y);
                    unsigned b10 = __float_as_uint(bv.z), b11 = __float_as_uint(bv.w);
                    int j0 = sub*4 + 2*q, j1 = j0 + 1;
#pragma unroll
                    for (int mt = 0; mt < 2; mt++) {
                        asm volatile(
                            "mma.sync.aligned.m16n8k8.row.col.f32.tf32.tf32.f32 "
                            "{%0,%1,%2,%3}, {%4,%5,%6,%7}, {%8,%9}, {%0,%1,%2,%3};"
                            : "+f"(acc[mt][j0][0]), "+f"(acc[mt][j0][1]),
                              "+f"(acc[mt][j0][2]), "+f"(acc[mt][j0][3])
                            : "r"(a[mt][0]), "r"(a[mt][1]), "r"(a[mt][2]), "r"(a[mt][3]),
                              "r"(b00), "r"(b01));
                        asm volatile(
                            "mma.sync.aligned.m16n8k8.row.col.f32.tf32.tf32.f32 "
                            "{%0,%1,%2,%3}, {%4,%5,%6,%7}, {%8,%9}, {%0,%1,%2,%3};"
                            : "+f"(acc[mt][j1][0]), "+f"(acc[mt][j1][1]),
                              "+f"(acc[mt][j1][2]), "+f"(acc[mt][j1][3])
                            : "r"(a[mt][0]), "r"(a[mt][1]), "r"(a[mt][2]), "r"(a[mt][3]),
                              "r"(b10), "r"(b11));
                    }
                }
            }
        }
    };

    issueA(0);
    issueB(0);
    if (p.totCh > 1) issueB(1);

    int gc = 0;
    for (int s = 0; s < p.nSt; s++) {
        mbar_wait(mbA, s & 1);
        int strideF = p.st[s].strideF;
        int kShift = p.st[s].shiftF;
        int nc = p.st[s].nCh;
        for (int c = 0; c < nc; c++, gc++) {
            mbar_wait(mbB[gc & 1], (gc >> 1) & 1);
            compute(strideF, kShift, c * 32, Bbuf[gc & 1]);
            __syncthreads();
            if (gc + 2 < p.totCh) issueB(gc + 2);
            if (c == nc - 1 && s + 1 < p.nSt) issueA(s + 1);
        }
    }

    // ---- epilogue: lane-paired float4 path ----
    bool isEven = ((tg & 1) == 0);
    int tbase = nb + (isEven ? tg : (tg - 1)) * 2;

    if (Yout) {
#pragma unroll
        for (int mt = 0; mt < 2; mt++) {
            int nA = r_base + m0 + mt * 16 + g;
            int nS = isEven ? nA : (nA + 8);
            bool vS = nS < p.nRows;
#pragma unroll
            for (int j = 0; j < 8; j++) {
                float a0 = acc[mt][j][0], a1 = acc[mt][j][1];
                float b0 = acc[mt][j][2], b1 = acc[mt][j][3];
                float na0 = __shfl_xor_sync(0xFFFFFFFFu, a0, 1);
                float na1 = __shfl_xor_sync(0xFFFFFFFFu, a1, 1);
                float nb0 = __shfl_xor_sync(0xFFFFFFFFu, b0, 1);
                float nb1 = __shfl_xor_sync(0xFFFFFFFFu, b1, 1);
                float4 a4 = isEven ? make_float4(a0, a1, na0, na1)
                                   : make_float4(nb0, nb1, b0, b1);
                if (vS)
                    *reinterpret_cast<float4*>(&Yout[(size_t)nS*128 + tbase + j*8]) = a4;
            }
        }
    } else {
#pragma unroll
        for (int mt = 0; mt < 2; mt++) {
            int eA = r_base + m0 + mt * 16 + g;
            int eS = isEven ? eA : (eA + 8);
            bool vS = eS < N_EDGES;
            int rS = vS ? p.row[eS] : 0;
            int cS = vS ? p.col[eS] : 0;
            float lsum = 0.f;
#pragma unroll
            for (int j = 0; j < 8; j++) {
                float a0 = acc[mt][j][0], a1 = acc[mt][j][1];
                float b0 = acc[mt][j][2], b1 = acc[mt][j][3];
                float na0 = __shfl_xor_sync(0xFFFFFFFFu, a0, 1);
                float na1 = __shfl_xor_sync(0xFFFFFFFFu, a1, 1);
                float nb0 = __shfl_xor_sync(0xFFFFFFFFu, b0, 1);
                float nb1 = __shfl_xor_sync(0xFFFFFFFFu, b1, 1);
                if (vS) {
                    float4 a4 = isEven ? make_float4(a0, a1, na0, na1)
                                       : make_float4(nb0, nb1, b0, b1);
                    int n4 = tbase + j*8;
                    float4 bias4 = *reinterpret_cast<const float4*>(&p.bias[n4]);
                    float4 yr = *reinterpret_cast<const float4*>(&p.Yr[(size_t)rS*128 + n4]);
                    float4 yc = *reinterpret_cast<const float4*>(&p.Yc[(size_t)cS*128 + n4]);
                    float4 m4 = make_float4(a4.x + bias4.x + yr.x + yc.x,
                                            a4.y + bias4.y + yr.y + yc.y,
                                            a4.z + bias4.z + yr.z + yc.z,
                                            a4.w + bias4.w + yr.w + yc.w);
                    float o0 = fmaxf(m4.x, 0.f), o1 = fmaxf(m4.y, 0.f);
                    float o2 = fmaxf(m4.z, 0.f), o3 = fmaxf(m4.w, 0.f);
                    *reinterpret_cast<float2*>(&p.e_out[(size_t)eS*128 + n4]) =
                        make_float2(o0, o1);
                    *reinterpret_cast<float2*>(&p.e_out[(size_t)eS*128 + n4 + 2]) =
                        make_float2(o2, o3);
                    red_add_v4(&p.xsum[(size_t)rS*128 + n4], m4);
                    if (p.ores) {
                        float4 w4 = *reinterpret_cast<const float4*>(&p.w2[n4]);
                        lsum = fmaf(o0, w4.x, fmaf(o1, w4.y,
                               fmaf(o2, w4.z, fmaf(o3, w4.w, lsum))));
                    }
                }
            }
            if (p.ores && vS) atomicAdd(&p.ores[eS], lsum);
        }
    }
}

// x_next = relu(xsum / max(cnt,1)); resets xsum
__global__ void node_update(float* __restrict__ xsum,
                            const int* __restrict__ cnt,
                            float* __restrict__ xout, int n_elems) {
    int i = blockIdx.x * blockDim.x + threadIdx.x;
    if (i >= n_elems) return;
    int node = i >> 7;
    float c = (float)max(cnt[node], 1);
    float v = xsum[i];
    xsum[i] = 0.f;
    xout[i] = fmaxf(v / c, 0.f);
}

__global__ void lin1_kernel(const float* __restrict__ x4,
                            const float* __restrict__ w,
                            const float* __restrict__ bb,
                            const float* __restrict__ x_org,
                            float* __restrict__ xout) {
    int n = blockIdx.x * blockDim.x + threadIdx.x;
    if (n >= N_NODES) return;
    float q0 = bb[0], q1 = bb[1], q2 = bb[2], q3 = bb[3];
    const float4* w4 = reinterpret_cast<const float4*>(w);       // w[k*4..k*4+3]
#pragma unroll 4
    for (int k = 0; k < 128; k++) {
        float v = x4[(size_t)n * 128 + k];
        float4 wv = w4[k];
        q0 = fmaf(v, wv.x, q0);
        q1 = fmaf(v, wv.y, q1);
        q2 = fmaf(v, wv.z, q2);
        q3 = fmaf(v, wv.w, q3);
    }
    float4 qr = reinterpret_cast<const float4*>(x_org)[n];
    float ow,ox,oy,oz;
    qmul4(q0,q1,q2,q3, qr.x, qr.y, qr.z, qr.w, ow,ox,oy,oz);
    float nn = sqrtf(ow*ow + ox*ox + oy*oy + oz*oz);
    nn = fmaxf(nn, 1e-12f);
    float inv = 1.f / nn;
    xout[n*4+0] = ow*inv; xout[n*4+1] = ox*inv;
    xout[n*4+2] = oy*inv; xout[n*4+3] = oz*inv;
}

__global__ void loss_kernel(const float* __restrict__ gt,
                            const float* __restrict__ x,
                            const int* __restrict__ row,
                            const int* __restrict__ col,
                            const float* __restrict__ beta_p,
                            float* __restrict__ loss_acc) {
    int e = blockIdx.x * blockDim.x + threadIdx.x;
    float local = 0.f;
    if (e < N_EDGES) {
        int r = row[e], c = col[e];
        const float4* g4 = reinterpret_cast<const float4*>(gt);
        float4 ga = g4[c];
        float4 gb = g4[r];
        float gw,gx,gy,gz;
        qmul4(ga.x, ga.y, ga.z, ga.w, gb.x, -gb.y, -gb.z, -gb.w, gw,gx,gy,gz);
        float4 xc = *reinterpret_cast<const float4*>(&x[c*4]);
        float4 xr = *reinterpret_cast<const float4*>(&x[r*4]);
        float xw,xx,xy,xz;
        qmul4(xc.x, xc.y, xc.z, xc.w, xr.x, -xr.y, -xr.z, -xr.w, xw,xx,xy,xz);
        float lw,lx,ly,lz;
        qmul4(gw,-gx,-gy,-gz, xw,xx,xy,xz, lw,lx,ly,lz);
        float nn = sqrtf(lw*lw + lx*lx + ly*ly + lz*lz);
        nn = fmaxf(nn, 1e-12f);
        lw /= nn; lx /= nn; ly /= nn; lz /= nn;
        float beta = beta_p[0];
        float d[4] = {fabsf(lw - 1.f), fabsf(lx), fabsf(ly), fabsf(lz)};
#pragma unroll
        for (int i = 0; i < 4; i++) {
            float v = d[i];
            local += (v < beta) ? (0.5f * v * v / beta) : (v - 0.5f * beta);
        }
    }
    __shared__ float sm[256];
    sm[threadIdx.x] = local;
    __syncthreads();
    for (int s = 128; s > 0; s >>= 1) {
        if (threadIdx.x < s) sm[threadIdx.x] += sm[threadIdx.x + s];
        __syncthreads();
    }
    if (threadIdx.x == 0) atomicAdd(loss_acc, sm[0]);
}

__global__ void finalize_kernel(const float* __restrict__ loss_acc,
                                const float* __restrict__ beta_p,
                                float* __restrict__ out) {
    out[OFF_LOSS] = loss_acc[0] / (float)(N_EDGES * 4);
    out[OFF_BETA] = beta_p[0];
}

// ---------------- host ----------------
extern "C" void kernel_launch(void* const* d_in, const int* in_sizes, int n_in,
                              void* d_out, int out_size) {
    const float* x_org     = (const float*)d_in[0];
    const float* edge_attr = (const float*)d_in[1];
    const float* gt_q      = (const float*)d_in[2];
    const float* beta      = (const float*)d_in[3];
    const float* node_feat = (const float*)d_in[4];
    const float* edge_feat = (const float*)d_in[5];
    const float* W1 = (const float*)d_in[6];
    const float* b1 = (const float*)d_in[7];
    const float* W2 = (const float*)d_in[8];
    const float* b2 = (const float*)d_in[9];
    const float* W3 = (const float*)d_in[10];
    const float* b3 = (const float*)d_in[11];
    const float* W4 = (const float*)d_in[12];
    const float* b4 = (const float*)d_in[13];
    const float* lin1_w = (const float*)d_in[14];
    const float* lin1_b = (const float*)d_in[15];
    const float* lin2_w = (const float*)d_in[16];
    const float* lin2_b = (const float*)d_in[17];
    const int* ei = (const int*)d_in[18];
    const int* row = ei;
    const int* col = ei + N_EDGES;

    float* out = (float*)d_out;
    float* x1 = out + OFF_X1;
    float* x2 = out + OFF_X2;
    float* x3 = out + OFF_X3;
    float* x4 = out + OFF_X4;
    float* e1 = out + OFF_E1;
    float* e2 = out + OFF_E2;
    float* e3 = out + OFF_E3;
    float* e4 = out + OFF_E4;

    float *xsum, *lossacc, *side, *nside, *PW, *Yr, *Yc;
    int* cnt;
    cudaGetSymbolAddress((void**)&xsum, g_xsum);
    cudaGetSymbolAddress((void**)&lossacc, g_loss);
    cudaGetSymbolAddress((void**)&cnt, g_cnt);
    cudaGetSymbolAddress((void**)&side, g_side);
    cudaGetSymbolAddress((void**)&nside, g_nside);
    cudaGetSymbolAddress((void**)&PW, g_PW);
    cudaGetSymbolAddress((void**)&Yr, g_Yr);
    cudaGetSymbolAddress((void**)&Yc, g_Yc);

    cudaFuncSetAttribute(gemm_k, cudaFuncAttributeMaxDynamicSharedMemorySize, SMEM_BYTES);

    zero_i<<<(N_NODES + 255)/256, 256>>>(cnt, N_NODES);
    zero_f<<<1, 32>>>(lossacc, 1);
    fill_f<<<(N_EDGES + 255)/256, 256>>>(out + OFF_RES, lin2_b, N_EDGES);
    prep_kernel<<<(N_EDGES + 255)/256, 256>>>(x_org, edge_attr, row, col, side, nside, cnt);

    // ---- one-shot weight permute (12 slots, 76 chunks) ----
    int pwo[13];
    {
        PermAll pp;
        pp.W[0]=W1; pp.W[1]=W2; pp.W[2]=W3; pp.W[3]=W4;
        int counts[12] = {5,5,5,4,4,5,8,8,8,8,8,8};
        pp.chOff[0] = 0;
        for (int i = 0; i < 12; i++) pp.chOff[i+1] = pp.chOff[i] + counts[i];
        for (int i = 0; i < 13; i++) pwo[i] = pp.chOff[i];
        auto setS = [&](int s, int w, int ns, int d0,int s0,int l0, int d1,int s1,int l1) {
            pp.wsel[s]=w; pp.nseg[s]=ns;
            pp.d0[s]=d0; pp.s0[s]=s0; pp.l0[s]=l0;
            pp.d1[s]=d1; pp.s1[s]=s1; pp.l1[s]=l1;
        };
        setS(0, 0, 2, 0,0,128,   128,128,4);   // g1r: nf_r + xorg_r
        setS(1, 0, 2, 0,132,128, 128,260,4);   // g1c: nf_c + xorg_c
        setS(2, 0, 2, 0,264,128, 128,392,4);   // g1e: ef + eam
        setS(3, 1, 1, 0,0,128,   0,0,0);       // g2r
        setS(4, 1, 1, 0,128,128, 0,0,0);       // g2c
        setS(5, 1, 2, 0,260,128, 128,256,4);   // g2e: e1 + eam
        setS(6, 2, 1, 0,0,256,   0,0,0);       // g3r
        setS(7, 2, 1, 0,256,256, 0,0,0);       // g3c
        setS(8, 2, 1, 0,512,256, 0,0,0);       // g3e
        setS(9, 3, 1, 0,0,256,   0,0,0);       // g4r
        setS(10,3, 1, 0,256,256, 0,0,0);       // g4c
        setS(11,3, 1, 0,512,256, 0,0,0);       // g4e
        permAll_kernel<<<(76*4096 + 255)/256, 256>>>(pp, PW);
    }

    const int EGRID = (N_EDGES + BM - 1) / BM;
    const int NGRID = (N_NODES + BM - 1) / BM;

    auto node_pair = [&](int slotR, int slotC, const float* t0, int sh0,
                         const float* t1, int sh1, bool t1side) {
        GP p{};
        p.st[0] = { t0, 128, 132, 4, sh0 };
        if (t1side)   { p.st[1] = { t1, 32, 36, 1, 0 };    p.nSt = 2; p.totCh = 5; }
        else if (t1)  { p.st[1] = { t1, 128, 132, 4, sh1 }; p.nSt = 2; p.totCh = 8; }
        else          { p.nSt = 1; p.totCh = 4; }
        p.PW  = PW + (size_t)pwo[slotR]*4096;
        p.PW2 = PW + (size_t)pwo[slotC]*4096;
        p.nRows = N_NODES; p.Yout = Yr; p.Yout2 = Yc;
        gemm_k<<<dim3(NGRID, 2), 256, SMEM_BYTES>>>(p);
    };
    auto edge_gemm = [&](int slot, const float* t0, int sh0, const float* t1, int sh1,
                         bool t1side, const float* bias, float* e_out,
                         const float* w2, float* ores) {
        GP p{};
        p.st[0] = { t0, 128, 132, 4, sh0 };
        if (t1side) { p.st[1] = { t1, 32, 36, 1, 0 };    p.nSt = 2; p.totCh = 5; }
        else        { p.st[1] = { t1, 128, 132, 4, sh1 }; p.nSt = 2; p.totCh = 8; }
        p.PW = PW + (size_t)pwo[slot]*4096; p.PW2 = p.PW;
        p.bias = bias; p.Yr = Yr; p.Yc = Yc;
        p.e_out = e_out; p.xsum = xsum;
        p.row = row; p.col = col;
        p.nRows = N_EDGES; p.Yout = nullptr; p.Yout2 = nullptr;
        p.w2 = w2; p.ores = ores;
        gemm_k<<<EGRID, 256, SMEM_BYTES>>>(p);
    };
    auto upd = [&](float* xout) {
        node_update<<<(N_NODES*128 + 255)/256, 256>>>(xsum, cnt, xout, N_NODES*128);
    };

    // Layer 1
    node_pair(0, 1, node_feat, 0, nside, 0, true);
    edge_gemm(2, edge_feat, 0, side, 0, true, b1, e1, nullptr, nullptr);
    upd(x1);
    // Layer 2
    node_pair(3, 4, x1, 2, nullptr, 0, false);
    edge_gemm(5, e1, 2, side, 0, true, b2, e2, nullptr, nullptr);
    upd(x2);
    // Layer 3
    node_pair(6, 7, x2, 2, x1, 2, false);
    edge_gemm(8, e2, 2, e1, 2, false, b3, e3, nullptr, nullptr);
    upd(x3);
    // Layer 4 (fused out_res = relu(m) @ lin2_w + lin2_b)
    node_pair(9, 10, x3, 2, x2, 2, false);
    edge_gemm(11, e3, 2, e2, 2, false, b4, e4, lin2_w, out + OFF_RES);
    upd(x4);

    lin1_kernel<<<(N_NODES + 255)/256, 256>>>(x4, lin1_w, lin1_b, x_org, out + OFF_X);
    loss_kernel<<<(N_EDGES + 255)/256, 256>>>(gt_q, out + OFF_X, row, col, beta, lossacc);
    finalize_kernel<<<1, 1>>>(lossacc, beta, out);

    (void)in_sizes; (void)n_in; (void)out_size;
}

// round 17
// speedup vs baseline: 1.3800x; 1.0343x over previous
#include <cuda_runtime.h>
#include <math.h>

#define N_NODES 10000
#define N_EDGES 200000

// ---- output offsets (pytree leaf order) ----
#define OFF_X     0
#define OFF_LOSS  40000
#define OFF_BETA  40001
#define OFF_RES   40002
#define OFF_X1    240002
#define OFF_X2    1520002
#define OFF_X3    2800002
#define OFF_X4    4080002
#define OFF_E1    5360002
#define OFF_E2    30960002
#define OFF_E3    56560002
#define OFF_E4    82160002

// ---- scratch ----
__device__ float g_xsum[N_NODES * 128];   // zero-init; invariant: zero after each launch
__device__ int   g_cnt[N_NODES];
__device__ float g_loss[1];
__device__ int   g_flags[4];              // per-layer node-completion counters (reset by upd)
// zero-init; only floats [0,4) of each 32-float row are ever written.
__device__ float g_side[N_EDGES * 32];
__device__ float g_nside[N_NODES * 32];
__device__ float g_Yr[N_NODES * 128];
__device__ float g_Yc[N_NODES * 128];
__device__ float g_PW[76 * 4096];         // permuted tf32 weights

__device__ __forceinline__ unsigned f2tf32(float f) {
    unsigned u;
    asm("cvt.rna.tf32.f32 %0, %1;" : "=r"(u) : "f"(f));
    return u;
}
__device__ __forceinline__ float tf32f(float f) { return __uint_as_float(f2tf32(f)); }

__device__ __forceinline__ void red_add_v4(float* p, float4 v) {
    asm volatile("red.global.add.v4.f32 [%0], {%1,%2,%3,%4};"
                 :: "l"(p), "f"(v.x), "f"(v.y), "f"(v.z), "f"(v.w) : "memory");
}

__device__ __forceinline__ void qmul4(float qw,float qx,float qy,float qz,
                                      float rw,float rx,float ry,float rz,
                                      float& ow,float& ox,float& oy,float& oz) {
    ow = qw*rw - qx*rx - qy*ry - qz*rz;
    ox = qw*rx + qx*rw + qy*rz - qz*ry;
    oy = qw*ry - qx*rz + qy*rw + qz*rx;
    oz = qw*rz + qx*ry - qy*rx + qz*rw;
}

// ---------------- small kernels ----------------
__global__ void zero_f(float* p, int n) {
    int i = blockIdx.x * blockDim.x + threadIdx.x;
    if (i < n) p[i] = 0.f;
}
__global__ void zero_i(int* p, int n) {
    int i = blockIdx.x * blockDim.x + threadIdx.x;
    if (i < n) p[i] = 0;
}
__global__ void fill_f(float* p, const float* val, int n) {
    int i = blockIdx.x * blockDim.x + threadIdx.x;
    if (i < n) p[i] = val[0];
}

// side (eam, tf32) + nside (xorg, tf32) + row counts — vectorized
__global__ void prep_kernel(const float* __restrict__ x_org,
                            const float* __restrict__ edge_attr,
                            const int* __restrict__ row,
                            const int* __restrict__ col,
                            float* __restrict__ side,
                            float* __restrict__ nside,
                            int* __restrict__ cnt) {
    int e = blockIdx.x * blockDim.x + threadIdx.x;
    const float4* x4p = reinterpret_cast<const float4*>(x_org);
    if (e < N_NODES) {
        float4 q = x4p[e];
        *reinterpret_cast<float4*>(&nside[(size_t)e * 32]) =
            make_float4(tf32f(q.x), tf32f(q.y), tf32f(q.z), tf32f(q.w));
    }
    if (e >= N_EDGES) return;
    int r = row[e], c = col[e];
    float4 qc = x4p[c];
    float4 qa = reinterpret_cast<const float4*>(edge_attr)[e];
    float4 qr = x4p[r];
    float tw,tx,ty,tz;
    qmul4(qc.x, -qc.y, -qc.z, -qc.w, qa.x, qa.y, qa.z, qa.w, tw,tx,ty,tz);
    float ow,ox,oy,oz;
    qmul4(tw,tx,ty,tz, qr.x, qr.y, qr.z, qr.w, ow,ox,oy,oz);
    *reinterpret_cast<float4*>(&side[(size_t)e * 32]) =
        make_float4(tf32f(ow), tf32f(ox), tf32f(oy), tf32f(oz));
    atomicAdd(&cnt[r], 1);
}

// ---- single-launch weight permuter for all 12 sub-GEMMs (76 chunks) ----
struct PermAll {
    const float* W[4];
    int chOff[13];
    int wsel[12];
    int nseg[12];
    int d0[12], s0[12], l0[12];
    int d1[12], s1[12], l1[12];
};
__global__ void permAll_kernel(const __grid_constant__ PermAll pp, float* __restrict__ PW) {
    int o = blockIdx.x * blockDim.x + threadIdx.x;
    if (o >= 76 * 4096) return;
    int gch = o >> 12, r = o & 4095;
    int slot = 0;
#pragma unroll
    for (int s = 0; s < 12; s++) if (gch >= pp.chOff[s+1]) slot = s + 1;
    int ch = gch - pp.chOff[slot];
    int wn = r >> 10, r2 = r & 1023;
    int ks = r2 >> 8, r3 = r2 & 255;
    int q  = r3 >> 7, r4 = r3 & 127;
    int lane = r4 >> 2, elem = r4 & 3;
    int g = lane >> 2, tg = lane & 3;
    int kp = ch*32 + ks*8 + tg + (elem & 1)*4;
    int n  = wn*32 + (2*q + (elem >> 1))*8 + g;
    const float* W = pp.W[pp.wsel[slot]];
    float v = 0.f;
    if (kp >= pp.d0[slot] && kp < pp.d0[slot] + pp.l0[slot])
        v = tf32f(W[(size_t)(pp.s0[slot] + kp - pp.d0[slot]) * 128 + n]);
    else if (pp.nseg[slot] > 1 && kp >= pp.d1[slot] && kp < pp.d1[slot] + pp.l1[slot])
        v = tf32f(W[(size_t)(pp.s1[slot] + kp - pp.d1[slot]) * 128 + n]);
    PW[o] = v;
}

// ---------------- fused node+edge tf32 GEMM (256 threads, 2 CTAs/SM) ----------------
struct Stage { const float* tab; int widthF; int strideF; int nCh; int shiftF; };
struct GP {
    Stage stN[2]; int nStN; int totChN;
    const float* PWr; const float* PWc;
    Stage stE[2]; int nStE; int totChE;
    const float* PWe;
    const float* bias;
    float* Yr; float* Yc;
    float* e_out; float* xsum;
    const int* row; const int* col;
    const float* w2; float* ores;
    int* flag; int nNodeBlocks; int nGridNode;
};

#define BM 128
#define A_BUF_F 16896     // 128 * 132 (single buffer, reused across stages)
#define B_BUF_F 4096
#define SMEM_FLOATS (A_BUF_F + 2*B_BUF_F)
#define SMEM_BYTES  (SMEM_FLOATS*4 + 32)

__device__ __forceinline__ void bulk_g2s(unsigned dst, const float* src, unsigned bytes,
                                         unsigned mbar) {
    asm volatile(
        "cp.async.bulk.shared::cluster.global.mbarrier::complete_tx::bytes [%0], [%1], %2, [%3];"
        :: "r"(dst), "l"(src), "r"(bytes), "r"(mbar) : "memory");
}
__device__ __forceinline__ void mbar_init(unsigned mbar, unsigned cnt) {
    asm volatile("mbarrier.init.shared.b64 [%0], %1;" :: "r"(mbar), "r"(cnt) : "memory");
}
__device__ __forceinline__ void mbar_expect(unsigned mbar, unsigned bytes) {
    asm volatile("mbarrier.arrive.expect_tx.shared.b64 _, [%0], %1;"
                 :: "r"(mbar), "r"(bytes) : "memory");
}
__device__ __forceinline__ void mbar_wait(unsigned mbar, unsigned parity) {
    asm volatile(
        "{\n\t.reg .pred P;\n\t"
        "WAIT_%=:\n\t"
        "mbarrier.try_wait.parity.acquire.cta.shared::cta.b64 P, [%0], %1, 0x989680;\n\t"
        "@P bra.uni DONE_%=;\n\t"
        "bra.uni WAIT_%=;\n\t"
        "DONE_%=:\n\t}"
        :: "r"(mbar), "r"(parity) : "memory");
}

__global__ void __launch_bounds__(256, 2)
gemm_fused(const __grid_constant__ GP p) {
    extern __shared__ __align__(16) float smem[];
    float* Abuf = smem;
    float* Bbuf[2] = { smem + A_BUF_F, smem + A_BUF_F + B_BUF_F };
    unsigned mbase = (unsigned)__cvta_generic_to_shared(smem + SMEM_FLOATS);
    unsigned mbA = mbase;
    unsigned mbB[2] = { mbase + 8, mbase + 16 };
    unsigned AbufU = (unsigned)__cvta_generic_to_shared(Abuf);
    unsigned BbufU[2] = { (unsigned)__cvta_generic_to_shared(Bbuf[0]),
                          (unsigned)__cvta_generic_to_shared(Bbuf[1]) };

    int bid = blockIdx.x;
    bool nodeMode = bid < 2 * p.nGridNode;
    Stage stages[2];
    const float* PW;
    float* Yout = nullptr;
    int nSt, totCh, nRows, r_base;
    if (nodeMode) {
        int sub = (bid >= p.nGridNode) ? 1 : 0;
        PW = sub ? p.PWc : p.PWr;
        Yout = sub ? p.Yc : p.Yr;
        r_base = (bid - sub * p.nGridNode) * BM;
        stages[0] = p.stN[0]; stages[1] = p.stN[1];
        nSt = p.nStN; totCh = p.totChN; nRows = N_NODES;
    } else {
        PW = p.PWe;
        r_base = (bid - 2 * p.nGridNode) * BM;
        stages[0] = p.stE[0]; stages[1] = p.stE[1];
        nSt = p.nStE; totCh = p.totChE; nRows = N_EDGES;
    }

    int tid = threadIdx.x;
    int lane = tid & 31, wrp = tid >> 5;

    if (tid == 0) {
        mbar_init(mbA, 1);
        mbar_init(mbB[0], 1); mbar_init(mbB[1], 1);
    }
    __syncthreads();

    int wm = wrp & 3, wn = wrp >> 2;      // wn in {0,1}
    int m0 = wm * 32, nb = wn * 64;
    int g = lane >> 2, tg = lane & 3;

    float acc[2][8][4];
#pragma unroll
    for (int mt = 0; mt < 2; mt++)
#pragma unroll
        for (int j = 0; j < 8; j++)
#pragma unroll
            for (int c = 0; c < 4; c++) acc[mt][j][c] = 0.f;

    auto issueA = [&](int s) {
        if (tid < 128) {
            Stage st = stages[s];
            int idx = min(r_base + tid, nRows - 1);
            const float* src = st.tab + (size_t)idx * st.widthF - st.shiftF;
            unsigned bytes = (unsigned)(st.widthF + (st.shiftF ? 4 : 0)) * 4u;
            bulk_g2s(AbufU + (unsigned)(tid * st.strideF * 4), src, bytes, mbA);
            if (tid == 0) mbar_expect(mbA, 128u * bytes);
        }
    };
    auto issueB = [&](int gc) {
        if (tid == 0) {
            bulk_g2s(BbufU[gc & 1], PW + (size_t)gc * 4096, 16384, mbB[gc & 1]);
            mbar_expect(mbB[gc & 1], 16384);
        }
    };
    auto compute = [&](int strideF, int kShift, int kkBase, const float* Bs) {
#pragma unroll
        for (int ks = 0; ks < 4; ks++) {
            int kk = kkBase + ks * 8 + kShift;
            unsigned a[2][4];
#pragma unroll
            for (int mt = 0; mt < 2; mt++) {
                int r = m0 + mt * 16;
                a[mt][0] = f2tf32(Abuf[(r + g    ) * strideF + kk + tg    ]);
                a[mt][1] = f2tf32(Abuf[(r + g + 8) * strideF + kk + tg    ]);
                a[mt][2] = f2tf32(Abuf[(r + g    ) * strideF + kk + tg + 4]);
                a[mt][3] = f2tf32(Abuf[(r + g + 8) * strideF + kk + tg + 4]);
            }
#pragma unroll
            for (int sub = 0; sub < 2; sub++) {
                int wnG = wn * 2 + sub;
#pragma unroll
                for (int q = 0; q < 2; q++) {
                    float4 bv = *reinterpret_cast<const float4*>(
                        &Bs[(((wnG*4 + ks)*2 + q)*32 + lane)*4]);
                    unsigned b00 = __float_as_uint(bv.x), b01 = __float_as_uint(bv.y);
                    unsigned b10 = __float_as_uint(bv.z), b11 = __float_as_uint(bv.w);
                    int j0 = sub*4 + 2*q, j1 = j0 + 1;
#pragma unroll
                    for (int mt = 0; mt < 2; mt++) {
                        asm volatile(
                            "mma.sync.aligned.m16n8k8.row.col.f32.tf32.tf32.f32 "
                            "{%0,%1,%2,%3}, {%4,%5,%6,%7}, {%8,%9}, {%0,%1,%2,%3};"
                            : "+f"(acc[mt][j0][0]), "+f"(acc[mt][j0][1]),
                              "+f"(acc[mt][j0][2]), "+f"(acc[mt][j0][3])
                            : "r"(a[mt][0]), "r"(a[mt][1]), "r"(a[mt][2]), "r"(a[mt][3]),
                              "r"(b00), "r"(b01));
                        asm volatile(
                            "mma.sync.aligned.m16n8k8.row.col.f32.tf32.tf32.f32 "
                            "{%0,%1,%2,%3}, {%4,%5,%6,%7}, {%8,%9}, {%0,%1,%2,%3};"
                            : "+f"(acc[mt][j1][0]), "+f"(acc[mt][j1][1]),
                              "+f"(acc[mt][j1][2]), "+f"(acc[mt][j1][3])
                            : "r"(a[mt][0]), "r"(a[mt][1]), "r"(a[mt][2]), "r"(a[mt][3]),
                              "r"(b10), "r"(b11));
                    }
                }
            }
        }
    };

    issueA(0);
    issueB(0);
    if (totCh > 1) issueB(1);

    int gc = 0;
    for (int s = 0; s < nSt; s++) {
        mbar_wait(mbA, s & 1);
        int strideF = stages[s].strideF;
        int kShift = stages[s].shiftF;
        int nc = stages[s].nCh;
        for (int c = 0; c < nc; c++, gc++) {
            mbar_wait(mbB[gc & 1], (gc >> 1) & 1);
            compute(strideF, kShift, c * 32, Bbuf[gc & 1]);
            __syncthreads();
            if (gc + 2 < totCh) issueB(gc + 2);
            if (c == nc - 1 && s + 1 < nSt) issueA(s + 1);
        }
    }

    // ---- epilogue: lane-paired float4 path ----
    bool isEven = ((tg & 1) == 0);
    int tbase = nb + (isEven ? tg : (tg - 1)) * 2;

    if (nodeMode) {
#pragma unroll
        for (int mt = 0; mt < 2; mt++) {
            int nA = r_base + m0 + mt * 16 + g;
            int nS = isEven ? nA : (nA + 8);
            bool vS = nS < N_NODES;
#pragma unroll
            for (int j = 0; j < 8; j++) {
                float a0 = acc[mt][j][0], a1 = acc[mt][j][1];
                float b0 = acc[mt][j][2], b1 = acc[mt][j][3];
                float na0 = __shfl_xor_sync(0xFFFFFFFFu, a0, 1);
                float na1 = __shfl_xor_sync(0xFFFFFFFFu, a1, 1);
                float nb0 = __shfl_xor_sync(0xFFFFFFFFu, b0, 1);
                float nb1 = __shfl_xor_sync(0xFFFFFFFFu, b1, 1);
                float4 a4 = isEven ? make_float4(a0, a1, na0, na1)
                                   : make_float4(nb0, nb1, b0, b1);
                if (vS)
                    *reinterpret_cast<float4*>(&Yout[(size_t)nS*128 + tbase + j*8]) = a4;
            }
        }
        __threadfence();
        __syncthreads();
        if (tid == 0) atomicAdd(p.flag, 1);
    } else {
        // wait for node sub-GEMMs to publish Yr/Yc
        if (tid == 0) {
            while (atomicAdd(p.flag, 0) < p.nNodeBlocks) __nanosleep(200);
        }
        __syncthreads();
        __threadfence();
#pragma unroll
        for (int mt = 0; mt < 2; mt++) {
            int eA = r_base + m0 + mt * 16 + g;
            int eS = isEven ? eA : (eA + 8);
            bool vS = eS < N_EDGES;
            int rS = vS ? p.row[eS] : 0;
            int cS = vS ? p.col[eS] : 0;
            float lsum = 0.f;
#pragma unroll
            for (int j = 0; j < 8; j++) {
                float a0 = acc[mt][j][0], a1 = acc[mt][j][1];
                float b0 = acc[mt][j][2], b1 = acc[mt][j][3];
                float na0 = __shfl_xor_sync(0xFFFFFFFFu, a0, 1);
                float na1 = __shfl_xor_sync(0xFFFFFFFFu, a1, 1);
                float nb0 = __shfl_xor_sync(0xFFFFFFFFu, b0, 1);
                float nb1 = __shfl_xor_sync(0xFFFFFFFFu, b1, 1);
                if (vS) {
                    float4 a4 = isEven ? make_float4(a0, a1, na0, na1)
                                       : make_float4(nb0, nb1, b0, b1);
                    int n4 = tbase + j*8;
                    float4 bias4 = *reinterpret_cast<const float4*>(&p.bias[n4]);
                    float4 yr = *reinterpret_cast<const float4*>(&p.Yr[(size_t)rS*128 + n4]);
                    float4 yc = *reinterpret_cast<const float4*>(&p.Yc[(size_t)cS*128 + n4]);
                    float4 m4 = make_float4(a4.x + bias4.x + yr.x + yc.x,
                                            a4.y + bias4.y + yr.y + yc.y,
                                            a4.z + bias4.z + yr.z + yc.z,
                                            a4.w + bias4.w + yr.w + yc.w);
                    float o0 = fmaxf(m4.x, 0.f), o1 = fmaxf(m4.y, 0.f);
                    float o2 = fmaxf(m4.z, 0.f), o3 = fmaxf(m4.w, 0.f);
                    *reinterpret_cast<float2*>(&p.e_out[(size_t)eS*128 + n4]) =
                        make_float2(o0, o1);
                    *reinterpret_cast<float2*>(&p.e_out[(size_t)eS*128 + n4 + 2]) =
                        make_float2(o2, o3);
                    red_add_v4(&p.xsum[(size_t)rS*128 + n4], m4);
                    if (p.ores) {
                        float4 w4 = *reinterpret_cast<const float4*>(&p.w2[n4]);
                        lsum = fmaf(o0, w4.x, fmaf(o1, w4.y,
                               fmaf(o2, w4.z, fmaf(o3, w4.w, lsum))));
                    }
                }
            }
            if (p.ores && vS) atomicAdd(&p.ores[eS], lsum);
        }
    }
}

// x_next = relu(xsum / max(cnt,1)); resets xsum + this layer's flag
__global__ void node_update(float* __restrict__ xsum,
                            const int* __restrict__ cnt,
                            float* __restrict__ xout,
                            int* __restrict__ flag, int n_elems) {
    int i = blockIdx.x * blockDim.x + threadIdx.x;
    if (i == 0) *flag = 0;
    if (i >= n_elems) return;
    int node = i >> 7;
    float c = (float)max(cnt[node], 1);
    float v = xsum[i];
    xsum[i] = 0.f;
    xout[i] = fmaxf(v / c, 0.f);
}

// layer-4 node_update fused with lin1 (x = normalize(qmul(x4 @ w + b, x_org)))
__global__ void upd4_lin1(float* __restrict__ xsum,
                          const int* __restrict__ cnt,
                          float* __restrict__ x4out,
                          const float* __restrict__ w,
                          const float* __restrict__ bb,
                          const float* __restrict__ x_org,
                          float* __restrict__ xout,
                          int* __restrict__ flag) {
    int i = blockIdx.x * 256 + threadIdx.x;
    if (i == 0) *flag = 0;
    int node = i >> 7, k = i & 127;
    float c = (float)max(cnt[node], 1);
    float v = xsum[i];
    xsum[i] = 0.f;
    float x = fmaxf(v / c, 0.f);
    x4out[i] = x;
    float4 wv = reinterpret_cast<const float4*>(w)[k];
    float p0 = x*wv.x, p1 = x*wv.y, p2 = x*wv.z, p3 = x*wv.w;
#pragma unroll
    for (int o = 16; o > 0; o >>= 1) {
        p0 += __shfl_down_sync(0xFFFFFFFFu, p0, o);
        p1 += __shfl_down_sync(0xFFFFFFFFu, p1, o);
        p2 += __shfl_down_sync(0xFFFFFFFFu, p2, o);
        p3 += __shfl_down_sync(0xFFFFFFFFu, p3, o);
    }
    __shared__ float red[2][4][4];
    int grp = threadIdx.x >> 7, wig = (threadIdx.x >> 5) & 3;
    if ((threadIdx.x & 31) == 0) {
        red[grp][wig][0] = p0; red[grp][wig][1] = p1;
        red[grp][wig][2] = p2; red[grp][wig][3] = p3;
    }
    __syncthreads();
    if ((threadIdx.x & 127) == 0) {
        float q0 = bb[0], q1 = bb[1], q2 = bb[2], q3 = bb[3];
#pragma unroll
        for (int wgi = 0; wgi < 4; wgi++) {
            q0 += red[grp][wgi][0]; q1 += red[grp][wgi][1];
            q2 += red[grp][wgi][2]; q3 += red[grp][wgi][3];
        }
        float4 qr = reinterpret_cast<const float4*>(x_org)[node];
        float ow,ox,oy,oz;
        qmul4(q0,q1,q2,q3, qr.x, qr.y, qr.z, qr.w, ow,ox,oy,oz);
        float nn = fmaxf(sqrtf(ow*ow + ox*ox + oy*oy + oz*oz), 1e-12f);
        float inv = 1.f / nn;
        *reinterpret_cast<float4*>(&xout[node*4]) =
            make_float4(ow*inv, ox*inv, oy*inv, oz*inv);
    }
}

__global__ void loss_kernel(const float* __restrict__ gt,
                            const float* __restrict__ x,
                            const int* __restrict__ row,
                            const int* __restrict__ col,
                            const float* __restrict__ beta_p,
                            float* __restrict__ loss_acc) {
    int e = blockIdx.x * blockDim.x + threadIdx.x;
    float local = 0.f;
    if (e < N_EDGES) {
        int r = row[e], c = col[e];
        const float4* g4 = reinterpret_cast<const float4*>(gt);
        float4 ga = g4[c];
        float4 gb = g4[r];
        float gw,gx,gy,gz;
        qmul4(ga.x, ga.y, ga.z, ga.w, gb.x, -gb.y, -gb.z, -gb.w, gw,gx,gy,gz);
        float4 xc = *reinterpret_cast<const float4*>(&x[c*4]);
        float4 xr = *reinterpret_cast<const float4*>(&x[r*4]);
        float xw,xx,xy,xz;
        qmul4(xc.x, xc.y, xc.z, xc.w, xr.x, -xr.y, -xr.z, -xr.w, xw,xx,xy,xz);
        float lw,lx,ly,lz;
        qmul4(gw,-gx,-gy,-gz, xw,xx,xy,xz, lw,lx,ly,lz);
        float nn = fmaxf(sqrtf(lw*lw + lx*lx + ly*ly + lz*lz), 1e-12f);
        lw /= nn; lx /= nn; ly /= nn; lz /= nn;
        float beta = beta_p[0];
        float d[4] = {fabsf(lw - 1.f), fabsf(lx), fabsf(ly), fabsf(lz)};
#pragma unroll
        for (int i = 0; i < 4; i++) {
            float v = d[i];
            local += (v < beta) ? (0.5f * v * v / beta) : (v - 0.5f * beta);
        }
    }
    __shared__ float sm[256];
    sm[threadIdx.x] = local;
    __syncthreads();
    for (int s = 128; s > 0; s >>= 1) {
        if (threadIdx.x < s) sm[threadIdx.x] += sm[threadIdx.x + s];
        __syncthreads();
    }
    if (threadIdx.x == 0) atomicAdd(loss_acc, sm[0]);
}

__global__ void finalize_kernel(const float* __restrict__ loss_acc,
                                const float* __restrict__ beta_p,
                                float* __restrict__ out) {
    out[OFF_LOSS] = loss_acc[0] / (float)(N_EDGES * 4);
    out[OFF_BETA] = beta_p[0];
}

// ---------------- host ----------------
extern "C" void kernel_launch(void* const* d_in, const int* in_sizes, int n_in,
                              void* d_out, int out_size) {
    const float* x_org     = (const float*)d_in[0];
    const float* edge_attr = (const float*)d_in[1];
    const float* gt_q      = (const float*)d_in[2];
    const float* beta      = (const float*)d_in[3];
    const float* node_feat = (const float*)d_in[4];
    const float* edge_feat = (const float*)d_in[5];
    const float* W1 = (const float*)d_in[6];
    const float* b1 = (const float*)d_in[7];
    const float* W2 = (const float*)d_in[8];
    const float* b2 = (const float*)d_in[9];
    const float* W3 = (const float*)d_in[10];
    const float* b3 = (const float*)d_in[11];
    const float* W4 = (const float*)d_in[12];
    const float* b4 = (const float*)d_in[13];
    const float* lin1_w = (const float*)d_in[14];
    const float* lin1_b = (const float*)d_in[15];
    const float* lin2_w = (const float*)d_in[16];
    const float* lin2_b = (const float*)d_in[17];
    const int* ei = (const int*)d_in[18];
    const int* row = ei;
    const int* col = ei + N_EDGES;

    float* out = (float*)d_out;
    float* x1 = out + OFF_X1;
    float* x2 = out + OFF_X2;
    float* x3 = out + OFF_X3;
    float* x4 = out + OFF_X4;
    float* e1 = out + OFF_E1;
    float* e2 = out + OFF_E2;
    float* e3 = out + OFF_E3;
    float* e4 = out + OFF_E4;

    float *xsum, *lossacc, *side, *nside, *PW, *Yr, *Yc;
    int *cnt, *flags;
    cudaGetSymbolAddress((void**)&xsum, g_xsum);
    cudaGetSymbolAddress((void**)&lossacc, g_loss);
    cudaGetSymbolAddress((void**)&cnt, g_cnt);
    cudaGetSymbolAddress((void**)&side, g_side);
    cudaGetSymbolAddress((void**)&nside, g_nside);
    cudaGetSymbolAddress((void**)&PW, g_PW);
    cudaGetSymbolAddress((void**)&Yr, g_Yr);
    cudaGetSymbolAddress((void**)&Yc, g_Yc);
    cudaGetSymbolAddress((void**)&flags, g_flags);

    cudaFuncSetAttribute(gemm_fused, cudaFuncAttributeMaxDynamicSharedMemorySize, SMEM_BYTES);

    zero_i<<<(N_NODES + 255)/256, 256>>>(cnt, N_NODES);
    zero_f<<<1, 32>>>(lossacc, 1);
    fill_f<<<(N_EDGES + 255)/256, 256>>>(out + OFF_RES, lin2_b, N_EDGES);
    prep_kernel<<<(N_EDGES + 255)/256, 256>>>(x_org, edge_attr, row, col, side, nside, cnt);

    // ---- one-shot weight permute (12 slots, 76 chunks) ----
    int pwo[13];
    {
        PermAll pp;
        pp.W[0]=W1; pp.W[1]=W2; pp.W[2]=W3; pp.W[3]=W4;
        int counts[12] = {5,5,5,4,4,5,8,8,8,8,8,8};
        pp.chOff[0] = 0;
        for (int i = 0; i < 12; i++) pp.chOff[i+1] = pp.chOff[i] + counts[i];
        for (int i = 0; i < 13; i++) pwo[i] = pp.chOff[i];
        auto setS = [&](int s, int w, int ns, int d0,int s0,int l0, int d1,int s1,int l1) {
            pp.wsel[s]=w; pp.nseg[s]=ns;
            pp.d0[s]=d0; pp.s0[s]=s0; pp.l0[s]=l0;
            pp.d1[s]=d1; pp.s1[s]=s1; pp.l1[s]=l1;
        };
        setS(0, 0, 2, 0,0,128,   128,128,4);   // g1r
        setS(1, 0, 2, 0,132,128, 128,260,4);   // g1c
        setS(2, 0, 2, 0,264,128, 128,392,4);   // g1e
        setS(3, 1, 1, 0,0,128,   0,0,0);       // g2r
        setS(4, 1, 1, 0,128,128, 0,0,0);       // g2c
        setS(5, 1, 2, 0,260,128, 128,256,4);   // g2e
        setS(6, 2, 1, 0,0,256,   0,0,0);       // g3r
        setS(7, 2, 1, 0,256,256, 0,0,0);       // g3c
        setS(8, 2, 1, 0,512,256, 0,0,0);       // g3e
        setS(9, 3, 1, 0,0,256,   0,0,0);       // g4r
        setS(10,3, 1, 0,256,256, 0,0,0);       // g4c
        setS(11,3, 1, 0,512,256, 0,0,0);       // g4e
        permAll_kernel<<<(76*4096 + 255)/256, 256>>>(pp, PW);
    }

    const int EGRID = (N_EDGES + BM - 1) / BM;   // 1563
    const int NGRID = (N_NODES + BM - 1) / BM;   // 79

    auto layer = [&](int slotR, int slotC, int slotE,
                     const float* tN0, int shN0, const float* tN1, int shN1, int nmode,
                     const float* tE0, int shE0, const float* tE1, int shE1, bool eSide,
                     const float* bias, float* e_out,
                     const float* w2, float* ores, int lidx) {
        GP p{};
        p.stN[0] = { tN0, 128, 132, 4, shN0 };
        if (nmode == 1)      { p.stN[1] = { tN1, 32, 36, 1, 0 };    p.nStN = 2; p.totChN = 5; }
        else if (nmode == 2) { p.stN[1] = { tN1, 128, 132, 4, shN1 }; p.nStN = 2; p.totChN = 8; }
        else                 { p.nStN = 1; p.totChN = 4; }
        p.PWr = PW + (size_t)pwo[slotR]*4096;
        p.PWc = PW + (size_t)pwo[slotC]*4096;
        p.stE[0] = { tE0, 128, 132, 4, shE0 };
        if (eSide) { p.stE[1] = { tE1, 32, 36, 1, 0 };    p.nStE = 2; p.totChE = 5; }
        else       { p.stE[1] = { tE1, 128, 132, 4, shE1 }; p.nStE = 2; p.totChE = 8; }
        p.PWe = PW + (size_t)pwo[slotE]*4096;
        p.bias = bias; p.Yr = Yr; p.Yc = Yc;
        p.e_out = e_out; p.xsum = xsum;
        p.row = row; p.col = col;
        p.w2 = w2; p.ores = ores;
        p.flag = flags + lidx; p.nNodeBlocks = 2 * NGRID; p.nGridNode = NGRID;
        gemm_fused<<<2*NGRID + EGRID, 256, SMEM_BYTES>>>(p);
    };
    auto upd = [&](float* xout, int lidx) {
        node_update<<<(N_NODES*128 + 255)/256, 256>>>(xsum, cnt, xout, flags + lidx,
                                                      N_NODES*128);
    };

    // Layer 1
    layer(0, 1, 2, node_feat, 0, nside, 0, 1,
          edge_feat, 0, side, 0, true, b1, e1, nullptr, nullptr, 0);
    upd(x1, 0);
    // Layer 2
    layer(3, 4, 5, x1, 2, nullptr, 0, 0,
          e1, 2, side, 0, true, b2, e2, nullptr, nullptr, 1);
    upd(x2, 1);
    // Layer 3
    layer(6, 7, 8, x2, 2, x1, 2, 2,
          e2, 2, e1, 2, false, b3, e3, nullptr, nullptr, 2);
    upd(x3, 2);
    // Layer 4 (fused out_res)
    layer(9, 10, 11, x3, 2, x2, 2, 2,
          e3, 2, e2, 2, false, b4, e4, lin2_w, out + OFF_RES, 3);
    upd4_lin1<<<(N_NODES*128)/256, 256>>>(xsum, cnt, x4, lin1_w, lin1_b, x_org,
                                          out + OFF_X, flags + 3);

    loss_kernel<<<(N_EDGES + 255)/256, 256>>>(gt_q, out + OFF_X, row, col, beta, lossacc);
    finalize_kernel<<<1, 1>>>(lossacc, beta, out);

    (void)in_sizes; (void)n_in; (void)out_size;
}